// round 1
// baseline (speedup 1.0000x reference)
#include <cuda_runtime.h>
#include <math.h>

// ---------------------------------------------------------------------------
// GPT forward, fp32 baseline.
// B=2, T=1024, C=1024, L=4, H=16, HD=64, V=50257. Full (unmasked) attention
// per the reference note. Output: last-position logits [2, 50257] fp32.
// ---------------------------------------------------------------------------

#define Bv 2
#define Tv 1024
#define Cv 1024
#define Lv 4
#define Hv 16
#define HDv 64
#define Vv 50257
#define BTv (Bv * Tv)   // 2048

// ---- scratch (device globals; no allocation allowed) ----------------------
__device__ float g_x[BTv * Cv];                       // residual stream  (8 MB)
__device__ float g_ln[BTv * Cv];                      // LN output        (8 MB)
__device__ float g_qkv[BTv * 3 * Cv];                 // qkv              (24 MB)
__device__ float g_att[(size_t)Bv * Hv * Tv * Tv];    // scores/probs     (134 MB)
__device__ float g_o[BTv * Cv];                       // attn output      (8 MB)
__device__ float g_fc[BTv * 4 * Cv];                  // fc activations   (32 MB)
__device__ float g_xf[Bv * Cv];                       // final LN rows

// ---------------------------------------------------------------------------
// embed: x[b,t,:] = wte[idx[b,t],:] + wpe[t,:]
// grid = BT blocks, 256 threads, 1 float4/thread (C/4 = 256)
// ---------------------------------------------------------------------------
__global__ void embed_kernel(const int* __restrict__ idx,
                             const float* __restrict__ wte,
                             const float* __restrict__ wpe,
                             float* __restrict__ x) {
    int row = blockIdx.x;
    int t = row & (Tv - 1);
    int tok = idx[row];
    const float4* a = (const float4*)(wte + (size_t)tok * Cv);
    const float4* p = (const float4*)(wpe + (size_t)t * Cv);
    float4 va = a[threadIdx.x];
    float4 vp = p[threadIdx.x];
    float4 r = make_float4(va.x + vp.x, va.y + vp.y, va.z + vp.z, va.w + vp.w);
    ((float4*)(x + (size_t)row * Cv))[threadIdx.x] = r;
}

// ---------------------------------------------------------------------------
// layernorm: one block per row, 256 threads, 4 elems each (C=1024)
// ---------------------------------------------------------------------------
__global__ void layernorm_kernel(const float* __restrict__ in, size_t in_stride,
                                 const float* __restrict__ w,
                                 const float* __restrict__ b,
                                 float* __restrict__ out, size_t out_stride) {
    const float* p = in + (size_t)blockIdx.x * in_stride;
    int tid = threadIdx.x;
    float4 v = ((const float4*)p)[tid];
    float s = v.x + v.y + v.z + v.w;
    float ss = v.x * v.x + v.y * v.y + v.z * v.z + v.w * v.w;

    __shared__ float sm1[8], sm2[8];
    int lane = tid & 31, wid = tid >> 5;
#pragma unroll
    for (int o = 16; o > 0; o >>= 1) {
        s += __shfl_down_sync(0xffffffffu, s, o);
        ss += __shfl_down_sync(0xffffffffu, ss, o);
    }
    if (lane == 0) { sm1[wid] = s; sm2[wid] = ss; }
    __syncthreads();
    if (wid == 0) {
        s = (lane < 8) ? sm1[lane] : 0.f;
        ss = (lane < 8) ? sm2[lane] : 0.f;
#pragma unroll
        for (int o = 4; o > 0; o >>= 1) {
            s += __shfl_down_sync(0xffffffffu, s, o);
            ss += __shfl_down_sync(0xffffffffu, ss, o);
        }
        if (lane == 0) { sm1[0] = s; sm2[0] = ss; }
    }
    __syncthreads();
    float mean = sm1[0] * (1.0f / Cv);
    float var = sm2[0] * (1.0f / Cv) - mean * mean;
    float rstd = rsqrtf(var + 1e-5f);
    float4 w4 = ((const float4*)w)[tid];
    float4 b4 = ((const float4*)b)[tid];
    float4 y;
    y.x = (v.x - mean) * rstd * w4.x + b4.x;
    y.y = (v.y - mean) * rstd * w4.y + b4.y;
    y.z = (v.z - mean) * rstd * w4.z + b4.z;
    y.w = (v.w - mean) * rstd * w4.w + b4.w;
    ((float4*)(out + (size_t)blockIdx.x * out_stride))[tid] = y;
}

// ---------------------------------------------------------------------------
// SGEMM: C[M,N] = A[M,K] @ W[N,K]^T + bias[N]  (+ residual | gelu)
// 128x128 block tile, BK=8, 256 threads, 8x8 per thread.
// EPI: 0 = bias only, 1 = bias + residual add, 2 = bias + exact GELU
// M,N multiples of 128; K multiple of 8.
// ---------------------------------------------------------------------------
__device__ __forceinline__ float gelu_f(float x) {
    return 0.5f * x * (1.0f + erff(x * 0.70710678118654752f));
}

template <int EPI>
__global__ __launch_bounds__(256)
void sgemm_kernel(const float* __restrict__ A, const float* __restrict__ W,
                  const float* __restrict__ bias, const float* __restrict__ res,
                  float* __restrict__ Cout, int M, int N, int K) {
    __shared__ __align__(16) float As[8][128];
    __shared__ __align__(16) float Bs[8][128];

    int tid = threadIdx.x;
    int tx = tid & 15;   // n-group
    int ty = tid >> 4;   // m-group
    const float* Ab = A + (size_t)(blockIdx.y * 128) * K;
    const float* Wb = W + (size_t)(blockIdx.x * 128) * K;
    int lrow = tid >> 1;          // 0..127
    int lcol = (tid & 1) * 4;     // 0 or 4

    float acc[8][8];
#pragma unroll
    for (int i = 0; i < 8; i++)
#pragma unroll
        for (int j = 0; j < 8; j++) acc[i][j] = 0.f;

    for (int k0 = 0; k0 < K; k0 += 8) {
        float4 av = *(const float4*)(Ab + (size_t)lrow * K + k0 + lcol);
        float4 wv = *(const float4*)(Wb + (size_t)lrow * K + k0 + lcol);
        As[lcol + 0][lrow] = av.x; As[lcol + 1][lrow] = av.y;
        As[lcol + 2][lrow] = av.z; As[lcol + 3][lrow] = av.w;
        Bs[lcol + 0][lrow] = wv.x; Bs[lcol + 1][lrow] = wv.y;
        Bs[lcol + 2][lrow] = wv.z; Bs[lcol + 3][lrow] = wv.w;
        __syncthreads();
#pragma unroll
        for (int k = 0; k < 8; k++) {
            float4 a0 = *(const float4*)&As[k][ty * 8];
            float4 a1 = *(const float4*)&As[k][ty * 8 + 4];
            float4 b0 = *(const float4*)&Bs[k][tx * 8];
            float4 b1 = *(const float4*)&Bs[k][tx * 8 + 4];
            float a[8] = {a0.x, a0.y, a0.z, a0.w, a1.x, a1.y, a1.z, a1.w};
            float bb[8] = {b0.x, b0.y, b0.z, b0.w, b1.x, b1.y, b1.z, b1.w};
#pragma unroll
            for (int i = 0; i < 8; i++)
#pragma unroll
                for (int j = 0; j < 8; j++) acc[i][j] = fmaf(a[i], bb[j], acc[i][j]);
        }
        __syncthreads();
    }

    int r0 = blockIdx.y * 128 + ty * 8;
    int c0 = blockIdx.x * 128 + tx * 8;
#pragma unroll
    for (int i = 0; i < 8; i++) {
#pragma unroll
        for (int j = 0; j < 8; j++) {
            float v = acc[i][j] + bias[c0 + j];
            if (EPI == 1) v += res[(size_t)(r0 + i) * N + c0 + j];
            if (EPI == 2) v = gelu_f(v);
            Cout[(size_t)(r0 + i) * N + c0 + j] = v;
        }
    }
}

// ---------------------------------------------------------------------------
// attention scores: S[z,i,j] = (1/8) * sum_d q[b,i,h,d] * k[b,j,h,d]
// z = b*H + h.  64x64 tile per block, full K=64 in smem.
// grid (T/64, T/64, B*H), 256 threads, 4x4 per thread.
// ---------------------------------------------------------------------------
__global__ __launch_bounds__(256)
void attn_scores_kernel(const float* __restrict__ qkv, float* __restrict__ att) {
    int z = blockIdx.z;
    int b = z >> 4;
    int h = z & 15;
    int i0 = blockIdx.y * 64, j0 = blockIdx.x * 64;
    const float* qb = qkv + ((size_t)b * Tv) * (3 * Cv) + h * HDv;
    const float* kb = qb + Cv;

    __shared__ __align__(16) float Qs[64][68];  // [d][i]
    __shared__ __align__(16) float Ks[64][68];  // [d][j]

    int tid = threadIdx.x;
#pragma unroll
    for (int it = 0; it < 4; ++it) {
        int u = tid + it * 256;
        int row = u >> 4;           // 0..63
        int dq = (u & 15) * 4;      // 0..60
        float4 qv = *(const float4*)(qb + (size_t)(i0 + row) * (3 * Cv) + dq);
        float4 kv = *(const float4*)(kb + (size_t)(j0 + row) * (3 * Cv) + dq);
        Qs[dq + 0][row] = qv.x; Qs[dq + 1][row] = qv.y;
        Qs[dq + 2][row] = qv.z; Qs[dq + 3][row] = qv.w;
        Ks[dq + 0][row] = kv.x; Ks[dq + 1][row] = kv.y;
        Ks[dq + 2][row] = kv.z; Ks[dq + 3][row] = kv.w;
    }
    __syncthreads();

    int tx = tid & 15, ty = tid >> 4;
    float acc[4][4] = {};
#pragma unroll
    for (int k = 0; k < 64; k++) {
        float4 a = *(const float4*)&Qs[k][ty * 4];
        float4 bv = *(const float4*)&Ks[k][tx * 4];
        float av[4] = {a.x, a.y, a.z, a.w};
        float bb[4] = {bv.x, bv.y, bv.z, bv.w};
#pragma unroll
        for (int ii = 0; ii < 4; ii++)
#pragma unroll
            for (int jj = 0; jj < 4; jj++) acc[ii][jj] = fmaf(av[ii], bb[jj], acc[ii][jj]);
    }
#pragma unroll
    for (int ii = 0; ii < 4; ii++)
#pragma unroll
        for (int jj = 0; jj < 4; jj++)
            att[((size_t)z * Tv + (i0 + ty * 4 + ii)) * Tv + (j0 + tx * 4 + jj)] =
                acc[ii][jj] * 0.125f;
}

// ---------------------------------------------------------------------------
// softmax over last dim (row length T=1024). grid = B*H*T rows.
// ---------------------------------------------------------------------------
__global__ void softmax_kernel(float* __restrict__ att) {
    float* p = att + (size_t)blockIdx.x * Tv;
    int tid = threadIdx.x;
    int lane = tid & 31, wid = tid >> 5;
    float4 v = ((float4*)p)[tid];

    __shared__ float sm[8];
    float m = fmaxf(fmaxf(v.x, v.y), fmaxf(v.z, v.w));
#pragma unroll
    for (int o = 16; o > 0; o >>= 1) m = fmaxf(m, __shfl_down_sync(0xffffffffu, m, o));
    if (lane == 0) sm[wid] = m;
    __syncthreads();
    if (wid == 0) {
        m = (lane < 8) ? sm[lane] : -1e30f;
#pragma unroll
        for (int o = 4; o > 0; o >>= 1) m = fmaxf(m, __shfl_down_sync(0xffffffffu, m, o));
        if (lane == 0) sm[0] = m;
    }
    __syncthreads();
    float gm = sm[0];
    __syncthreads();

    v.x = __expf(v.x - gm); v.y = __expf(v.y - gm);
    v.z = __expf(v.z - gm); v.w = __expf(v.w - gm);
    float s = v.x + v.y + v.z + v.w;
#pragma unroll
    for (int o = 16; o > 0; o >>= 1) s += __shfl_down_sync(0xffffffffu, s, o);
    if (lane == 0) sm[wid] = s;
    __syncthreads();
    if (wid == 0) {
        s = (lane < 8) ? sm[lane] : 0.f;
#pragma unroll
        for (int o = 4; o > 0; o >>= 1) s += __shfl_down_sync(0xffffffffu, s, o);
        if (lane == 0) sm[0] = s;
    }
    __syncthreads();
    float inv = 1.0f / sm[0];
    v.x *= inv; v.y *= inv; v.z *= inv; v.w *= inv;
    ((float4*)p)[tid] = v;
}

// ---------------------------------------------------------------------------
// O[b,i,h,:] = sum_j att[z,i,j] * v[b,j,h,:]   written into [B*T, C] layout.
// 64(i) x 64(d) tile per block, K-loop over j in chunks of 32.
// grid (T/64, B*H), 256 threads, 4x4 per thread.
// ---------------------------------------------------------------------------
__global__ __launch_bounds__(256)
void attn_av_kernel(const float* __restrict__ att, const float* __restrict__ qkv,
                    float* __restrict__ o) {
    int z = blockIdx.y;
    int b = z >> 4;
    int h = z & 15;
    int i0 = blockIdx.x * 64;
    const float* vb = qkv + ((size_t)b * Tv) * (3 * Cv) + 2 * Cv + h * HDv;
    const float* ab = att + (size_t)z * Tv * Tv;

    __shared__ __align__(16) float As[32][68];  // [j][i]
    __shared__ __align__(16) float Vs[32][68];  // [j][d]

    int tid = threadIdx.x;
    int tx = tid & 15, ty = tid >> 4;
    float acc[4][4] = {};

    for (int j0 = 0; j0 < Tv; j0 += 32) {
#pragma unroll
        for (int it = 0; it < 2; ++it) {
            int u = tid + it * 256;
            // att tile: 64 i rows x 32 j
            int ar = u >> 3;            // 0..63
            int aj = (u & 7) * 4;       // 0..28
            float4 av = *(const float4*)(ab + (size_t)(i0 + ar) * Tv + j0 + aj);
            As[aj + 0][ar] = av.x; As[aj + 1][ar] = av.y;
            As[aj + 2][ar] = av.z; As[aj + 3][ar] = av.w;
            // v tile: 32 j rows x 64 d
            int vr = u >> 4;            // 0..31
            int dq = (u & 15) * 4;      // 0..60
            float4 vv = *(const float4*)(vb + (size_t)(j0 + vr) * (3 * Cv) + dq);
            *(float4*)&Vs[vr][dq] = vv;
        }
        __syncthreads();
#pragma unroll
        for (int k = 0; k < 32; k++) {
            float4 a = *(const float4*)&As[k][ty * 4];
            float4 bv = *(const float4*)&Vs[k][tx * 4];
            float av[4] = {a.x, a.y, a.z, a.w};
            float bb[4] = {bv.x, bv.y, bv.z, bv.w};
#pragma unroll
            for (int ii = 0; ii < 4; ii++)
#pragma unroll
                for (int jj = 0; jj < 4; jj++)
                    acc[ii][jj] = fmaf(av[ii], bb[jj], acc[ii][jj]);
        }
        __syncthreads();
    }
#pragma unroll
    for (int ii = 0; ii < 4; ii++)
#pragma unroll
        for (int jj = 0; jj < 4; jj++)
            o[((size_t)b * Tv + i0 + ty * 4 + ii) * Cv + h * HDv + tx * 4 + jj] =
                acc[ii][jj];
}

// ---------------------------------------------------------------------------
// logits: out[b,v] = dot(xf[b,:], wte[v,:]).  One warp per vocab row, both b.
// ---------------------------------------------------------------------------
__global__ void logits_kernel(const float* __restrict__ xf,
                              const float* __restrict__ wte,
                              float* __restrict__ out) {
    int warp = (blockIdx.x * blockDim.x + threadIdx.x) >> 5;
    int lane = threadIdx.x & 31;
    if (warp >= Vv) return;
    const float4* w4 = (const float4*)(wte + (size_t)warp * Cv);
    const float4* x0 = (const float4*)xf;
    const float4* x1 = (const float4*)(xf + Cv);
    float s0 = 0.f, s1 = 0.f;
#pragma unroll
    for (int i = lane; i < Cv / 4; i += 32) {
        float4 w = w4[i];
        float4 a = x0[i];
        float4 c = x1[i];
        s0 += w.x * a.x + w.y * a.y + w.z * a.z + w.w * a.w;
        s1 += w.x * c.x + w.y * c.y + w.z * c.z + w.w * c.w;
    }
#pragma unroll
    for (int o = 16; o > 0; o >>= 1) {
        s0 += __shfl_down_sync(0xffffffffu, s0, o);
        s1 += __shfl_down_sync(0xffffffffu, s1, o);
    }
    if (lane == 0) {
        out[warp] = s0;
        out[Vv + warp] = s1;
    }
}

// ---------------------------------------------------------------------------
// launch
// ---------------------------------------------------------------------------
extern "C" void kernel_launch(void* const* d_in, const int* in_sizes, int n_in,
                              void* d_out, int out_size) {
    const int* idx = (const int*)d_in[0];
    const float* wte = (const float*)d_in[1];
    const float* wpe = (const float*)d_in[2];
    const float* ln1_w = (const float*)d_in[3];
    const float* ln1_b = (const float*)d_in[4];
    const float* attn_w = (const float*)d_in[5];
    const float* attn_b = (const float*)d_in[6];
    const float* proj_w = (const float*)d_in[7];
    const float* proj_b = (const float*)d_in[8];
    const float* ln2_w = (const float*)d_in[9];
    const float* ln2_b = (const float*)d_in[10];
    const float* fc_w = (const float*)d_in[11];
    const float* fc_b = (const float*)d_in[12];
    const float* fc2_w = (const float*)d_in[13];
    const float* fc2_b = (const float*)d_in[14];
    const float* lnf_w = (const float*)d_in[15];
    const float* lnf_b = (const float*)d_in[16];
    float* out = (float*)d_out;

    float* x;    cudaGetSymbolAddress((void**)&x, g_x);
    float* ln;   cudaGetSymbolAddress((void**)&ln, g_ln);
    float* qkv;  cudaGetSymbolAddress((void**)&qkv, g_qkv);
    float* att;  cudaGetSymbolAddress((void**)&att, g_att);
    float* o;    cudaGetSymbolAddress((void**)&o, g_o);
    float* fc;   cudaGetSymbolAddress((void**)&fc, g_fc);
    float* xf;   cudaGetSymbolAddress((void**)&xf, g_xf);

    embed_kernel<<<BTv, 256>>>(idx, wte, wpe, x);

    for (int l = 0; l < Lv; ++l) {
        layernorm_kernel<<<BTv, 256>>>(x, Cv, ln1_w + l * Cv, ln1_b + l * Cv, ln, Cv);
        sgemm_kernel<0><<<dim3(3 * Cv / 128, BTv / 128), 256>>>(
            ln, attn_w + (size_t)l * 3 * Cv * Cv, attn_b + l * 3 * Cv, nullptr,
            qkv, BTv, 3 * Cv, Cv);
        attn_scores_kernel<<<dim3(Tv / 64, Tv / 64, Bv * Hv), 256>>>(qkv, att);
        softmax_kernel<<<Bv * Hv * Tv, 256>>>(att);
        attn_av_kernel<<<dim3(Tv / 64, Bv * Hv), 256>>>(att, qkv, o);
        sgemm_kernel<1><<<dim3(Cv / 128, BTv / 128), 256>>>(
            o, proj_w + (size_t)l * Cv * Cv, proj_b + l * Cv, x, x, BTv, Cv, Cv);
        layernorm_kernel<<<BTv, 256>>>(x, Cv, ln2_w + l * Cv, ln2_b + l * Cv, ln, Cv);
        sgemm_kernel<2><<<dim3(4 * Cv / 128, BTv / 128), 256>>>(
            ln, fc_w + (size_t)l * 4 * Cv * Cv, fc_b + l * 4 * Cv, nullptr,
            fc, BTv, 4 * Cv, Cv);
        sgemm_kernel<1><<<dim3(Cv / 128, BTv / 128), 256>>>(
            fc, fc2_w + (size_t)l * Cv * 4 * Cv, fc2_b + l * Cv, x, x, BTv, Cv, 4 * Cv);
    }

    // final LN on the two last-position rows only
    layernorm_kernel<<<Bv, 256>>>(x + (size_t)(Tv - 1) * Cv, (size_t)Tv * Cv,
                                  lnf_w, lnf_b, xf, Cv);
    // logits for last position, tied lm_head
    int warps_needed = Vv;
    int blocks = (warps_needed * 32 + 255) / 256;
    logits_kernel<<<blocks, 256>>>(xf, wte, out);
}

// round 2
// speedup vs baseline: 5.2671x; 5.2671x over previous
#include <cuda_runtime.h>
#include <cuda_fp16.h>
#include <math.h>
#include <stdint.h>

// ---------------------------------------------------------------------------
// GPT forward. Tensor-core (fp16 mma.sync, fp32 accum) for all GEMMs.
// B=2, T=1024, C=1024, L=4, H=16, HD=64, V=50257. Unmasked attention.
// ---------------------------------------------------------------------------

#define Bv 2
#define Tv 1024
#define Cv 1024
#define Lv 4
#define Hv 16
#define HDv 64
#define Vv 50257
#define BTv 2048
#define KQKV (3 * Cv)

// ---- scratch ---------------------------------------------------------------
__device__ float  g_x[BTv * Cv];                       // residual (fp32)
__device__ __half g_ln[BTv * Cv];                      // LN out (half)
__device__ __half g_qkv[BTv * 3 * Cv];                 // qkv (half)
__device__ float  g_att[(size_t)Bv * Hv * Tv * Tv];    // scores fp32
__device__ __half g_p[(size_t)Bv * Hv * Tv * Tv];      // probs half
__device__ __half g_o[BTv * Cv];                       // attn out half
__device__ __half g_fc[BTv * 4 * Cv];                  // fc act half
__device__ float  g_xf[Bv * Cv];
// half weights
__device__ __half g_wa[Lv * 3 * Cv * Cv];
__device__ __half g_wp[Lv * Cv * Cv];
__device__ __half g_wf[Lv * 4 * Cv * Cv];
__device__ __half g_wf2[Lv * 4 * Cv * Cv];

// ---- PTX helpers ------------------------------------------------------------
__device__ __forceinline__ uint32_t cvta_s(const void* p) {
    return (uint32_t)__cvta_generic_to_shared(p);
}
__device__ __forceinline__ void cp_async16(uint32_t s, const void* g) {
    asm volatile("cp.async.cg.shared.global [%0], [%1], 16;" ::"r"(s), "l"(g));
}
__device__ __forceinline__ void cp_commit() {
    asm volatile("cp.async.commit_group;");
}
template <int N>
__device__ __forceinline__ void cp_wait() {
    asm volatile("cp.async.wait_group %0;" ::"n"(N));
}
__device__ __forceinline__ void ldsm_x4(uint32_t& r0, uint32_t& r1, uint32_t& r2,
                                        uint32_t& r3, uint32_t a) {
    asm volatile("ldmatrix.sync.aligned.m8n8.x4.shared.b16 {%0,%1,%2,%3}, [%4];"
                 : "=r"(r0), "=r"(r1), "=r"(r2), "=r"(r3) : "r"(a));
}
__device__ __forceinline__ void ldsm_x2(uint32_t& r0, uint32_t& r1, uint32_t a) {
    asm volatile("ldmatrix.sync.aligned.m8n8.x2.shared.b16 {%0,%1}, [%2];"
                 : "=r"(r0), "=r"(r1) : "r"(a));
}
__device__ __forceinline__ void ldsm_x2t(uint32_t& r0, uint32_t& r1, uint32_t a) {
    asm volatile("ldmatrix.sync.aligned.m8n8.x2.trans.shared.b16 {%0,%1}, [%2];"
                 : "=r"(r0), "=r"(r1) : "r"(a));
}
__device__ __forceinline__ void mma16816(float* c, uint32_t a0, uint32_t a1,
                                         uint32_t a2, uint32_t a3, uint32_t b0,
                                         uint32_t b1) {
    asm volatile(
        "mma.sync.aligned.m16n8k16.row.col.f32.f16.f16.f32 "
        "{%0,%1,%2,%3}, {%4,%5,%6,%7}, {%8,%9}, {%0,%1,%2,%3};"
        : "+f"(c[0]), "+f"(c[1]), "+f"(c[2]), "+f"(c[3])
        : "r"(a0), "r"(a1), "r"(a2), "r"(a3), "r"(b0), "r"(b1));
}
// swizzled half-offset within a tile of 64-half rows (8 x 16B chunks per row)
__device__ __forceinline__ uint32_t sw(int row, int kcol) {
    return (uint32_t)((row << 6) + ((((kcol >> 3) ^ (row & 7)) << 3) + (kcol & 7)));
}
__device__ __forceinline__ float gelu_f(float x) {
    return 0.5f * x * (1.0f + erff(x * 0.70710678118654752f));
}

// ---------------------------------------------------------------------------
// fp32 -> fp16 convert (weights)
// ---------------------------------------------------------------------------
__global__ void f2h_kernel(const float* __restrict__ s, __half* __restrict__ d,
                           int n4) {
    int i = blockIdx.x * blockDim.x + threadIdx.x;
    if (i < n4) {
        float4 v = ((const float4*)s)[i];
        __half2* o = (__half2*)(d + (size_t)i * 4);
        o[0] = __floats2half2_rn(v.x, v.y);
        o[1] = __floats2half2_rn(v.z, v.w);
    }
}

// ---------------------------------------------------------------------------
// embed
// ---------------------------------------------------------------------------
__global__ void embed_kernel(const int* __restrict__ idx,
                             const float* __restrict__ wte,
                             const float* __restrict__ wpe,
                             float* __restrict__ x) {
    int row = blockIdx.x;
    int t = row & (Tv - 1);
    int tok = idx[row];
    float4 va = ((const float4*)(wte + (size_t)tok * Cv))[threadIdx.x];
    float4 vp = ((const float4*)(wpe + (size_t)t * Cv))[threadIdx.x];
    ((float4*)(x + (size_t)row * Cv))[threadIdx.x] =
        make_float4(va.x + vp.x, va.y + vp.y, va.z + vp.z, va.w + vp.w);
}

// ---------------------------------------------------------------------------
// layernorm (templated output type)
// ---------------------------------------------------------------------------
template <typename OT>
__global__ void layernorm_kernel(const float* __restrict__ in, size_t in_stride,
                                 const float* __restrict__ w,
                                 const float* __restrict__ b,
                                 OT* __restrict__ out, size_t out_stride) {
    const float* p = in + (size_t)blockIdx.x * in_stride;
    int tid = threadIdx.x;
    float4 v = ((const float4*)p)[tid];
    float s = v.x + v.y + v.z + v.w;
    float ss = v.x * v.x + v.y * v.y + v.z * v.z + v.w * v.w;

    __shared__ float sm1[8], sm2[8];
    int lane = tid & 31, wid = tid >> 5;
#pragma unroll
    for (int o = 16; o > 0; o >>= 1) {
        s += __shfl_down_sync(0xffffffffu, s, o);
        ss += __shfl_down_sync(0xffffffffu, ss, o);
    }
    if (lane == 0) { sm1[wid] = s; sm2[wid] = ss; }
    __syncthreads();
    if (wid == 0) {
        s = (lane < 8) ? sm1[lane] : 0.f;
        ss = (lane < 8) ? sm2[lane] : 0.f;
#pragma unroll
        for (int o = 4; o > 0; o >>= 1) {
            s += __shfl_down_sync(0xffffffffu, s, o);
            ss += __shfl_down_sync(0xffffffffu, ss, o);
        }
        if (lane == 0) { sm1[0] = s; sm2[0] = ss; }
    }
    __syncthreads();
    float mean = sm1[0] * (1.0f / Cv);
    float var = sm2[0] * (1.0f / Cv) - mean * mean;
    float rstd = rsqrtf(var + 1e-5f);
    float4 w4 = ((const float4*)w)[tid];
    float4 b4 = ((const float4*)b)[tid];
    float y0 = (v.x - mean) * rstd * w4.x + b4.x;
    float y1 = (v.y - mean) * rstd * w4.y + b4.y;
    float y2 = (v.z - mean) * rstd * w4.z + b4.z;
    float y3 = (v.w - mean) * rstd * w4.w + b4.w;
    OT* op = out + (size_t)blockIdx.x * out_stride + tid * 4;
    if (sizeof(OT) == 2) {
        __half2* hp = (__half2*)op;
        hp[0] = __floats2half2_rn(y0, y1);
        hp[1] = __floats2half2_rn(y2, y3);
    } else {
        float4* fp = (float4*)op;
        *fp = make_float4(y0, y1, y2, y3);
    }
}

// ---------------------------------------------------------------------------
// Dense HGEMM: out[M,N] = A[M,K](half) @ W[N,K](half)^T + bias
// Block tile 256x128, BK=64, 256 threads, warp tile 64x64.
// EPI 0: half out (qkv). EPI 1: fp32 residual in-place. EPI 2: gelu, half out.
// ---------------------------------------------------------------------------
#define BM 256
#define BN 128
#define BKH 64

template <int EPI>
__global__ __launch_bounds__(256) void hgemm_kernel(
    const __half* __restrict__ A, const __half* __restrict__ W,
    const float* __restrict__ bias, float* __restrict__ resio,
    __half* __restrict__ outh, int M, int N, int K) {
    extern __shared__ __align__(16) __half smx[];
    __half* As = smx;                 // 2 * 256*64
    __half* Bs = smx + 2 * BM * BKH;  // 2 * 128*64
    const int tid = threadIdx.x;
    const int lane = tid & 31;
    const int w = tid >> 5;
    const int wm = w >> 1;  // 0..3
    const int wn = w & 1;   // 0..1

    const __half* Ab = A + (size_t)(blockIdx.y * BM) * K;
    const __half* Wb = W + (size_t)(blockIdx.x * BN) * K;
    uint32_t sA = cvta_s(As);
    uint32_t sB = cvta_s(Bs);

    float acc[4][8][4];
#pragma unroll
    for (int i = 0; i < 4; i++)
#pragma unroll
        for (int j = 0; j < 8; j++)
#pragma unroll
            for (int q = 0; q < 4; q++) acc[i][j][q] = 0.f;

    const int KT = K / BKH;

    // prologue: stage 0
    {
        int koff = 0;
#pragma unroll
        for (int i = 0; i < 8; i++) {
            int g = tid + i * 256; int r = g >> 3; int c = g & 7;
            cp_async16(sA + sw(r, c * 8) * 2, Ab + (size_t)r * K + koff + c * 8);
        }
#pragma unroll
        for (int i = 0; i < 4; i++) {
            int g = tid + i * 256; int r = g >> 3; int c = g & 7;
            cp_async16(sB + sw(r, c * 8) * 2, Wb + (size_t)r * K + koff + c * 8);
        }
        cp_commit();
    }

    for (int kt = 0; kt < KT; ++kt) {
        int cur = kt & 1;
        if (kt + 1 < KT) {
            int nxt = cur ^ 1;
            int koff = (kt + 1) * BKH;
#pragma unroll
            for (int i = 0; i < 8; i++) {
                int g = tid + i * 256; int r = g >> 3; int c = g & 7;
                cp_async16(sA + (nxt * BM * BKH + sw(r, c * 8)) * 2,
                           Ab + (size_t)r * K + koff + c * 8);
            }
#pragma unroll
            for (int i = 0; i < 4; i++) {
                int g = tid + i * 256; int r = g >> 3; int c = g & 7;
                cp_async16(sB + (nxt * BN * BKH + sw(r, c * 8)) * 2,
                           Wb + (size_t)r * K + koff + c * 8);
            }
            cp_commit();
            cp_wait<1>();
        } else {
            cp_wait<0>();
        }
        __syncthreads();

        uint32_t aB = sA + (uint32_t)(cur * BM * BKH * 2);
        uint32_t bB = sB + (uint32_t)(cur * BN * BKH * 2);
#pragma unroll
        for (int ks = 0; ks < 4; ++ks) {
            int k0 = ks * 16;
            uint32_t af[4][4];
#pragma unroll
            for (int mt = 0; mt < 4; ++mt) {
                int r = wm * 64 + mt * 16 + ((lane >> 3) & 1) * 8 + (lane & 7);
                int kc = k0 + ((lane >> 4) << 3);
                ldsm_x4(af[mt][0], af[mt][1], af[mt][2], af[mt][3],
                        aB + sw(r, kc) * 2);
            }
            uint32_t bf[8][2];
#pragma unroll
            for (int nt = 0; nt < 8; ++nt) {
                int l = lane & 15;
                int r = wn * 64 + nt * 8 + (l & 7);
                int kc = k0 + ((l >> 3) << 3);
                ldsm_x2(bf[nt][0], bf[nt][1], bB + sw(r, kc) * 2);
            }
#pragma unroll
            for (int mt = 0; mt < 4; ++mt)
#pragma unroll
                for (int nt = 0; nt < 8; ++nt)
                    mma16816(acc[mt][nt], af[mt][0], af[mt][1], af[mt][2],
                             af[mt][3], bf[nt][0], bf[nt][1]);
        }
        __syncthreads();
    }

    // epilogue
    int g = lane >> 2, t = lane & 3;
#pragma unroll
    for (int mt = 0; mt < 4; ++mt) {
        int r0 = blockIdx.y * BM + wm * 64 + mt * 16 + g;
#pragma unroll
        for (int nt = 0; nt < 8; ++nt) {
            int col = blockIdx.x * BN + wn * 64 + nt * 8 + 2 * t;
            float b0 = bias[col], b1 = bias[col + 1];
            float d0 = acc[mt][nt][0] + b0, d1 = acc[mt][nt][1] + b1;
            float d2 = acc[mt][nt][2] + b0, d3 = acc[mt][nt][3] + b1;
            if (EPI == 0) {
                *(__half2*)&outh[(size_t)r0 * N + col] = __floats2half2_rn(d0, d1);
                *(__half2*)&outh[(size_t)(r0 + 8) * N + col] = __floats2half2_rn(d2, d3);
            } else if (EPI == 1) {
                float2* p0 = (float2*)&resio[(size_t)r0 * N + col];
                float2 v0 = *p0; v0.x += d0; v0.y += d1; *p0 = v0;
                float2* p1 = (float2*)&resio[(size_t)(r0 + 8) * N + col];
                float2 v1 = *p1; v1.x += d2; v1.y += d3; *p1 = v1;
            } else {
                *(__half2*)&outh[(size_t)r0 * N + col] =
                    __floats2half2_rn(gelu_f(d0), gelu_f(d1));
                *(__half2*)&outh[(size_t)(r0 + 8) * N + col] =
                    __floats2half2_rn(gelu_f(d2), gelu_f(d3));
            }
        }
    }
}

// ---------------------------------------------------------------------------
// scores: S[z,i,j] = 0.125 * Q[i,:] . K[j,:]   (128x128 tile, K=64)
// grid (T/128 j, T/128 i, B*H), 256 thr, warp tile 64x32 (2m x 4n warps)
// ---------------------------------------------------------------------------
__global__ __launch_bounds__(256) void scores_kernel(
    const __half* __restrict__ qkv, float* __restrict__ att) {
    __shared__ __align__(16) __half Qs[128 * 64];
    __shared__ __align__(16) __half Ks[128 * 64];
    int tid = threadIdx.x, lane = tid & 31, w = tid >> 5;
    int wm = w >> 2, wn = w & 3;
    int z = blockIdx.z, b = z >> 4, h = z & 15;
    const __half* qb = qkv + ((size_t)(b * Tv + blockIdx.y * 128)) * KQKV + h * HDv;
    const __half* kb =
        qkv + ((size_t)(b * Tv + blockIdx.x * 128)) * KQKV + Cv + h * HDv;
    uint32_t sQ = cvta_s(Qs), sK = cvta_s(Ks);
#pragma unroll
    for (int i = 0; i < 4; i++) {
        int g = tid + i * 256; int r = g >> 3; int c = g & 7;
        cp_async16(sQ + sw(r, c * 8) * 2, qb + (size_t)r * KQKV + c * 8);
        cp_async16(sK + sw(r, c * 8) * 2, kb + (size_t)r * KQKV + c * 8);
    }
    cp_commit();
    cp_wait<0>();
    __syncthreads();

    float acc[4][4][4];
#pragma unroll
    for (int i = 0; i < 4; i++)
#pragma unroll
        for (int j = 0; j < 4; j++)
#pragma unroll
            for (int q = 0; q < 4; q++) acc[i][j][q] = 0.f;

#pragma unroll
    for (int ks = 0; ks < 4; ++ks) {
        int k0 = ks * 16;
        uint32_t af[4][4];
#pragma unroll
        for (int mt = 0; mt < 4; ++mt) {
            int r = wm * 64 + mt * 16 + ((lane >> 3) & 1) * 8 + (lane & 7);
            int kc = k0 + ((lane >> 4) << 3);
            ldsm_x4(af[mt][0], af[mt][1], af[mt][2], af[mt][3], sQ + sw(r, kc) * 2);
        }
        uint32_t bf[4][2];
#pragma unroll
        for (int nt = 0; nt < 4; ++nt) {
            int l = lane & 15;
            int r = wn * 32 + nt * 8 + (l & 7);
            int kc = k0 + ((l >> 3) << 3);
            ldsm_x2(bf[nt][0], bf[nt][1], sK + sw(r, kc) * 2);
        }
#pragma unroll
        for (int mt = 0; mt < 4; ++mt)
#pragma unroll
            for (int nt = 0; nt < 4; ++nt)
                mma16816(acc[mt][nt], af[mt][0], af[mt][1], af[mt][2], af[mt][3],
                         bf[nt][0], bf[nt][1]);
    }

    int g = lane >> 2, t = lane & 3;
#pragma unroll
    for (int mt = 0; mt < 4; ++mt) {
        int i0 = blockIdx.y * 128 + wm * 64 + mt * 16 + g;
#pragma unroll
        for (int nt = 0; nt < 4; ++nt) {
            int j0 = blockIdx.x * 128 + wn * 32 + nt * 8 + 2 * t;
            float2* p0 = (float2*)&att[((size_t)z * Tv + i0) * Tv + j0];
            *p0 = make_float2(acc[mt][nt][0] * 0.125f, acc[mt][nt][1] * 0.125f);
            float2* p1 = (float2*)&att[((size_t)z * Tv + i0 + 8) * Tv + j0];
            *p1 = make_float2(acc[mt][nt][2] * 0.125f, acc[mt][nt][3] * 0.125f);
        }
    }
}

// ---------------------------------------------------------------------------
// softmax fp32 in -> half probs out
// ---------------------------------------------------------------------------
__global__ void softmax_kernel(const float* __restrict__ att,
                               __half* __restrict__ probs) {
    const float* p = att + (size_t)blockIdx.x * Tv;
    int tid = threadIdx.x;
    int lane = tid & 31, wid = tid >> 5;
    float4 v = ((const float4*)p)[tid];

    __shared__ float smr[8];
    float m = fmaxf(fmaxf(v.x, v.y), fmaxf(v.z, v.w));
#pragma unroll
    for (int o = 16; o > 0; o >>= 1) m = fmaxf(m, __shfl_down_sync(0xffffffffu, m, o));
    if (lane == 0) smr[wid] = m;
    __syncthreads();
    if (wid == 0) {
        m = (lane < 8) ? smr[lane] : -1e30f;
#pragma unroll
        for (int o = 4; o > 0; o >>= 1) m = fmaxf(m, __shfl_down_sync(0xffffffffu, m, o));
        if (lane == 0) smr[0] = m;
    }
    __syncthreads();
    float gm = smr[0];
    __syncthreads();

    v.x = __expf(v.x - gm); v.y = __expf(v.y - gm);
    v.z = __expf(v.z - gm); v.w = __expf(v.w - gm);
    float s = v.x + v.y + v.z + v.w;
#pragma unroll
    for (int o = 16; o > 0; o >>= 1) s += __shfl_down_sync(0xffffffffu, s, o);
    if (lane == 0) smr[wid] = s;
    __syncthreads();
    if (wid == 0) {
        s = (lane < 8) ? smr[lane] : 0.f;
#pragma unroll
        for (int o = 4; o > 0; o >>= 1) s += __shfl_down_sync(0xffffffffu, s, o);
        if (lane == 0) smr[0] = s;
    }
    __syncthreads();
    float inv = 1.0f / smr[0];
    __half2* op = (__half2*)(probs + (size_t)blockIdx.x * Tv + tid * 4);
    op[0] = __floats2half2_rn(v.x * inv, v.y * inv);
    op[1] = __floats2half2_rn(v.z * inv, v.w * inv);
}

// ---------------------------------------------------------------------------
// AV: O[i,d] = sum_j P[i,j] V[j,d].  Block 128(i) x 64(d), BK=64 over j.
// warps 4m x 2n, warp tile 32x32. B via ldmatrix.trans on V[j][d].
// ---------------------------------------------------------------------------
__global__ __launch_bounds__(256) void av_kernel(const __half* __restrict__ probs,
                                                 const __half* __restrict__ qkv,
                                                 __half* __restrict__ o) {
    __shared__ __align__(16) __half Ps[2 * 128 * 64];
    __shared__ __align__(16) __half Vs[2 * 64 * 64];
    int tid = threadIdx.x, lane = tid & 31, w = tid >> 5;
    int wm = w >> 1, wn = w & 1;
    int z = blockIdx.y, b = z >> 4, h = z & 15;
    const __half* ab = probs + (size_t)z * Tv * Tv + (size_t)(blockIdx.x * 128) * Tv;
    const __half* vb = qkv + ((size_t)b * Tv) * KQKV + 2 * Cv + h * HDv;
    uint32_t sP = cvta_s(Ps), sV = cvta_s(Vs);

    float acc[2][4][4];
#pragma unroll
    for (int i = 0; i < 2; i++)
#pragma unroll
        for (int j = 0; j < 4; j++)
#pragma unroll
            for (int q = 0; q < 4; q++) acc[i][j][q] = 0.f;

    const int KT = Tv / BKH;  // 16

    // prologue stage 0
    {
#pragma unroll
        for (int i = 0; i < 4; i++) {
            int g = tid + i * 256; int r = g >> 3; int c = g & 7;
            cp_async16(sP + sw(r, c * 8) * 2, ab + (size_t)r * Tv + c * 8);
        }
#pragma unroll
        for (int i = 0; i < 2; i++) {
            int g = tid + i * 256; int r = g >> 3; int c = g & 7;
            cp_async16(sV + sw(r, c * 8) * 2, vb + (size_t)r * KQKV + c * 8);
        }
        cp_commit();
    }

    for (int kt = 0; kt < KT; ++kt) {
        int cur = kt & 1;
        if (kt + 1 < KT) {
            int nxt = cur ^ 1;
            int koff = (kt + 1) * BKH;
#pragma unroll
            for (int i = 0; i < 4; i++) {
                int g = tid + i * 256; int r = g >> 3; int c = g & 7;
                cp_async16(sP + (nxt * 128 * 64 + sw(r, c * 8)) * 2,
                           ab + (size_t)r * Tv + koff + c * 8);
            }
#pragma unroll
            for (int i = 0; i < 2; i++) {
                int g = tid + i * 256; int r = g >> 3; int c = g & 7;
                cp_async16(sV + (nxt * 64 * 64 + sw(r, c * 8)) * 2,
                           vb + (size_t)(koff + r) * KQKV + c * 8);
            }
            cp_commit();
            cp_wait<1>();
        } else {
            cp_wait<0>();
        }
        __syncthreads();

        uint32_t pB = sP + (uint32_t)(cur * 128 * 64 * 2);
        uint32_t vB = sV + (uint32_t)(cur * 64 * 64 * 2);
#pragma unroll
        for (int ks = 0; ks < 4; ++ks) {
            int k0 = ks * 16;
            uint32_t af[2][4];
#pragma unroll
            for (int mt = 0; mt < 2; ++mt) {
                int r = wm * 32 + mt * 16 + ((lane >> 3) & 1) * 8 + (lane & 7);
                int kc = k0 + ((lane >> 4) << 3);
                ldsm_x4(af[mt][0], af[mt][1], af[mt][2], af[mt][3],
                        pB + sw(r, kc) * 2);
            }
            uint32_t bf[4][2];
#pragma unroll
            for (int nt = 0; nt < 4; ++nt) {
                int l = lane & 15;
                int r = k0 + l;               // rows j = k0..k0+15
                int n0 = wn * 32 + nt * 8;    // d chunk
                ldsm_x2t(bf[nt][0], bf[nt][1], vB + sw(r, n0) * 2);
            }
#pragma unroll
            for (int mt = 0; mt < 2; ++mt)
#pragma unroll
                for (int nt = 0; nt < 4; ++nt)
                    mma16816(acc[mt][nt], af[mt][0], af[mt][1], af[mt][2],
                             af[mt][3], bf[nt][0], bf[nt][1]);
        }
        __syncthreads();
    }

    int g = lane >> 2, t = lane & 3;
#pragma unroll
    for (int mt = 0; mt < 2; ++mt) {
        int i0 = blockIdx.x * 128 + wm * 32 + mt * 16 + g;
#pragma unroll
        for (int nt = 0; nt < 4; ++nt) {
            int d = wn * 32 + nt * 8 + 2 * t;
            *(__half2*)&o[((size_t)b * Tv + i0) * Cv + h * HDv + d] =
                __floats2half2_rn(acc[mt][nt][0], acc[mt][nt][1]);
            *(__half2*)&o[((size_t)b * Tv + i0 + 8) * Cv + h * HDv + d] =
                __floats2half2_rn(acc[mt][nt][2], acc[mt][nt][3]);
        }
    }
}

// ---------------------------------------------------------------------------
// logits GEMV (fp32, tied wte)
// ---------------------------------------------------------------------------
__global__ void logits_kernel(const float* __restrict__ xf,
                              const float* __restrict__ wte,
                              float* __restrict__ out) {
    int warp = (blockIdx.x * blockDim.x + threadIdx.x) >> 5;
    int lane = threadIdx.x & 31;
    if (warp >= Vv) return;
    const float4* w4 = (const float4*)(wte + (size_t)warp * Cv);
    const float4* x0 = (const float4*)xf;
    const float4* x1 = (const float4*)(xf + Cv);
    float s0 = 0.f, s1 = 0.f;
#pragma unroll
    for (int i = lane; i < Cv / 4; i += 32) {
        float4 w = w4[i];
        float4 a = x0[i];
        float4 c = x1[i];
        s0 += w.x * a.x + w.y * a.y + w.z * a.z + w.w * a.w;
        s1 += w.x * c.x + w.y * c.y + w.z * c.z + w.w * c.w;
    }
#pragma unroll
    for (int o = 16; o > 0; o >>= 1) {
        s0 += __shfl_down_sync(0xffffffffu, s0, o);
        s1 += __shfl_down_sync(0xffffffffu, s1, o);
    }
    if (lane == 0) {
        out[warp] = s0;
        out[Vv + warp] = s1;
    }
}

// ---------------------------------------------------------------------------
// launch
// ---------------------------------------------------------------------------
extern "C" void kernel_launch(void* const* d_in, const int* in_sizes, int n_in,
                              void* d_out, int out_size) {
    const int* idx = (const int*)d_in[0];
    const float* wte = (const float*)d_in[1];
    const float* wpe = (const float*)d_in[2];
    const float* ln1_w = (const float*)d_in[3];
    const float* ln1_b = (const float*)d_in[4];
    const float* attn_w = (const float*)d_in[5];
    const float* attn_b = (const float*)d_in[6];
    const float* proj_w = (const float*)d_in[7];
    const float* proj_b = (const float*)d_in[8];
    const float* ln2_w = (const float*)d_in[9];
    const float* ln2_b = (const float*)d_in[10];
    const float* fc_w = (const float*)d_in[11];
    const float* fc_b = (const float*)d_in[12];
    const float* fc2_w = (const float*)d_in[13];
    const float* fc2_b = (const float*)d_in[14];
    const float* lnf_w = (const float*)d_in[15];
    const float* lnf_b = (const float*)d_in[16];
    float* out = (float*)d_out;

    float* x;   cudaGetSymbolAddress((void**)&x, g_x);
    __half* ln; cudaGetSymbolAddress((void**)&ln, g_ln);
    __half* qkv; cudaGetSymbolAddress((void**)&qkv, g_qkv);
    float* att; cudaGetSymbolAddress((void**)&att, g_att);
    __half* pr; cudaGetSymbolAddress((void**)&pr, g_p);
    __half* o;  cudaGetSymbolAddress((void**)&o, g_o);
    __half* fc; cudaGetSymbolAddress((void**)&fc, g_fc);
    float* xf;  cudaGetSymbolAddress((void**)&xf, g_xf);
    __half* wa; cudaGetSymbolAddress((void**)&wa, g_wa);
    __half* wp; cudaGetSymbolAddress((void**)&wp, g_wp);
    __half* wf; cudaGetSymbolAddress((void**)&wf, g_wf);
    __half* wf2; cudaGetSymbolAddress((void**)&wf2, g_wf2);

    static int attr_done = 0;
    const int HSM = 2 * (BM * BKH + BN * BKH) * 2;  // 98304 bytes
    if (!attr_done) {
        cudaFuncSetAttribute(hgemm_kernel<0>, cudaFuncAttributeMaxDynamicSharedMemorySize, HSM);
        cudaFuncSetAttribute(hgemm_kernel<1>, cudaFuncAttributeMaxDynamicSharedMemorySize, HSM);
        cudaFuncSetAttribute(hgemm_kernel<2>, cudaFuncAttributeMaxDynamicSharedMemorySize, HSM);
        attr_done = 1;
    }

    // weight conversion
    {
        int n4a = Lv * 3 * Cv * Cv / 4;
        f2h_kernel<<<(n4a + 255) / 256, 256>>>(attn_w, wa, n4a);
        int n4p = Lv * Cv * Cv / 4;
        f2h_kernel<<<(n4p + 255) / 256, 256>>>(proj_w, wp, n4p);
        int n4f = Lv * 4 * Cv * Cv / 4;
        f2h_kernel<<<(n4f + 255) / 256, 256>>>(fc_w, wf, n4f);
        f2h_kernel<<<(n4f + 255) / 256, 256>>>(fc2_w, wf2, n4f);
    }

    embed_kernel<<<BTv, 256>>>(idx, wte, wpe, x);

    for (int l = 0; l < Lv; ++l) {
        layernorm_kernel<__half><<<BTv, 256>>>(x, Cv, ln1_w + l * Cv, ln1_b + l * Cv, ln, Cv);
        hgemm_kernel<0><<<dim3(3 * Cv / BN, BTv / BM), 256, HSM>>>(
            ln, wa + (size_t)l * 3 * Cv * Cv, attn_b + l * 3 * Cv, nullptr, qkv,
            BTv, 3 * Cv, Cv);
        scores_kernel<<<dim3(Tv / 128, Tv / 128, Bv * Hv), 256>>>(qkv, att);
        softmax_kernel<<<Bv * Hv * Tv, 256>>>(att, pr);
        av_kernel<<<dim3(Tv / 128, Bv * Hv), 256>>>(pr, qkv, o);
        hgemm_kernel<1><<<dim3(Cv / BN, BTv / BM), 256, HSM>>>(
            o, wp + (size_t)l * Cv * Cv, proj_b + l * Cv, x, nullptr, BTv, Cv, Cv);
        layernorm_kernel<__half><<<BTv, 256>>>(x, Cv, ln2_w + l * Cv, ln2_b + l * Cv, ln, Cv);
        hgemm_kernel<2><<<dim3(4 * Cv / BN, BTv / BM), 256, HSM>>>(
            ln, wf + (size_t)l * 4 * Cv * Cv, fc_b + l * 4 * Cv, nullptr, fc, BTv,
            4 * Cv, Cv);
        hgemm_kernel<1><<<dim3(Cv / BN, BTv / BM), 256, HSM>>>(
            fc, wf2 + (size_t)l * 4 * Cv * Cv, fc2_b + l * Cv, x, nullptr, BTv, Cv,
            4 * Cv);
    }

    layernorm_kernel<float><<<Bv, 256>>>(x + (size_t)(Tv - 1) * Cv, (size_t)Tv * Cv,
                                         lnf_w, lnf_b, xf, Cv);
    int blocks = (Vv * 32 + 255) / 256;
    logits_kernel<<<blocks, 256>>>(xf, wte, out);
}

// round 4
// speedup vs baseline: 7.9175x; 1.5032x over previous
#include <cuda_runtime.h>
#include <cuda_fp16.h>
#include <math.h>
#include <stdint.h>

// ---------------------------------------------------------------------------
// GPT forward. fp16 mma.sync tensor cores + fused flash attention.
// B=2, T=1024, C=1024, L=4, H=16, HD=64, V=50257. Unmasked attention.
// ---------------------------------------------------------------------------

#define Bv 2
#define Tv 1024
#define Cv 1024
#define Lv 4
#define Hv 16
#define HDv 64
#define Vv 50257
#define BTv 2048
#define KQKV (3 * Cv)

// ---- scratch ---------------------------------------------------------------
__device__ float  g_x[BTv * Cv];
__device__ __half g_ln[BTv * Cv];
__device__ __half g_qkv[BTv * 3 * Cv];
__device__ __half g_o[BTv * Cv];
__device__ __half g_fc[BTv * 4 * Cv];
__device__ float  g_xf[Bv * Cv];
__device__ __half g_wa[Lv * 3 * Cv * Cv];
__device__ __half g_wp[Lv * Cv * Cv];
__device__ __half g_wf[Lv * 4 * Cv * Cv];
__device__ __half g_wf2[Lv * 4 * Cv * Cv];

// ---- PTX helpers ------------------------------------------------------------
__device__ __forceinline__ uint32_t cvta_s(const void* p) {
    return (uint32_t)__cvta_generic_to_shared(p);
}
__device__ __forceinline__ void cp_async16(uint32_t s, const void* g) {
    asm volatile("cp.async.cg.shared.global [%0], [%1], 16;" ::"r"(s), "l"(g));
}
__device__ __forceinline__ void cp_commit() {
    asm volatile("cp.async.commit_group;");
}
template <int N>
__device__ __forceinline__ void cp_wait() {
    asm volatile("cp.async.wait_group %0;" ::"n"(N));
}
__device__ __forceinline__ void ldsm_x4(uint32_t& r0, uint32_t& r1, uint32_t& r2,
                                        uint32_t& r3, uint32_t a) {
    asm volatile("ldmatrix.sync.aligned.m8n8.x4.shared.b16 {%0,%1,%2,%3}, [%4];"
                 : "=r"(r0), "=r"(r1), "=r"(r2), "=r"(r3) : "r"(a));
}
__device__ __forceinline__ void ldsm_x2(uint32_t& r0, uint32_t& r1, uint32_t a) {
    asm volatile("ldmatrix.sync.aligned.m8n8.x2.shared.b16 {%0,%1}, [%2];"
                 : "=r"(r0), "=r"(r1) : "r"(a));
}
__device__ __forceinline__ void ldsm_x4t(uint32_t& r0, uint32_t& r1, uint32_t& r2,
                                         uint32_t& r3, uint32_t a) {
    asm volatile("ldmatrix.sync.aligned.m8n8.x4.trans.shared.b16 {%0,%1,%2,%3}, [%4];"
                 : "=r"(r0), "=r"(r1), "=r"(r2), "=r"(r3) : "r"(a));
}
__device__ __forceinline__ void mma16816(float* c, uint32_t a0, uint32_t a1,
                                         uint32_t a2, uint32_t a3, uint32_t b0,
                                         uint32_t b1) {
    asm volatile(
        "mma.sync.aligned.m16n8k16.row.col.f32.f16.f16.f32 "
        "{%0,%1,%2,%3}, {%4,%5,%6,%7}, {%8,%9}, {%0,%1,%2,%3};"
        : "+f"(c[0]), "+f"(c[1]), "+f"(c[2]), "+f"(c[3])
        : "r"(a0), "r"(a1), "r"(a2), "r"(a3), "r"(b0), "r"(b1));
}
// FIXED pack: full 32-bit reinterpret of a half2 (was __half2_raw(...).x,
// which truncated to the low 16 bits and zeroed every odd P element).
__device__ __forceinline__ uint32_t pack_half2(float a, float b) {
    __half2 h = __floats2half2_rn(a, b);
    return *reinterpret_cast<uint32_t*>(&h);
}
// swizzled half-offset; tile row = 64 halves (8 x 16B chunks)
__device__ __forceinline__ uint32_t sw(int row, int kcol) {
    return (uint32_t)((row << 6) + ((((kcol >> 3) ^ (row & 7)) << 3) + (kcol & 7)));
}
__device__ __forceinline__ float gelu_f(float x) {
    return 0.5f * x * (1.0f + erff(x * 0.70710678118654752f));
}

// ---------------------------------------------------------------------------
__global__ void f2h_kernel(const float* __restrict__ s, __half* __restrict__ d,
                           int n4) {
    int i = blockIdx.x * blockDim.x + threadIdx.x;
    if (i < n4) {
        float4 v = ((const float4*)s)[i];
        __half2* o = (__half2*)(d + (size_t)i * 4);
        o[0] = __floats2half2_rn(v.x, v.y);
        o[1] = __floats2half2_rn(v.z, v.w);
    }
}

__global__ void embed_kernel(const int* __restrict__ idx,
                             const float* __restrict__ wte,
                             const float* __restrict__ wpe,
                             float* __restrict__ x) {
    int row = blockIdx.x;
    int t = row & (Tv - 1);
    int tok = idx[row];
    float4 va = ((const float4*)(wte + (size_t)tok * Cv))[threadIdx.x];
    float4 vp = ((const float4*)(wpe + (size_t)t * Cv))[threadIdx.x];
    ((float4*)(x + (size_t)row * Cv))[threadIdx.x] =
        make_float4(va.x + vp.x, va.y + vp.y, va.z + vp.z, va.w + vp.w);
}

// ---------------------------------------------------------------------------
template <typename OT>
__global__ void layernorm_kernel(const float* __restrict__ in, size_t in_stride,
                                 const float* __restrict__ w,
                                 const float* __restrict__ b,
                                 OT* __restrict__ out, size_t out_stride) {
    const float* p = in + (size_t)blockIdx.x * in_stride;
    int tid = threadIdx.x;
    float4 v = ((const float4*)p)[tid];
    float s = v.x + v.y + v.z + v.w;
    float ss = v.x * v.x + v.y * v.y + v.z * v.z + v.w * v.w;

    __shared__ float sm1[8], sm2[8];
    int lane = tid & 31, wid = tid >> 5;
#pragma unroll
    for (int o = 16; o > 0; o >>= 1) {
        s += __shfl_down_sync(0xffffffffu, s, o);
        ss += __shfl_down_sync(0xffffffffu, ss, o);
    }
    if (lane == 0) { sm1[wid] = s; sm2[wid] = ss; }
    __syncthreads();
    if (wid == 0) {
        s = (lane < 8) ? sm1[lane] : 0.f;
        ss = (lane < 8) ? sm2[lane] : 0.f;
#pragma unroll
        for (int o = 4; o > 0; o >>= 1) {
            s += __shfl_down_sync(0xffffffffu, s, o);
            ss += __shfl_down_sync(0xffffffffu, ss, o);
        }
        if (lane == 0) { sm1[0] = s; sm2[0] = ss; }
    }
    __syncthreads();
    float mean = sm1[0] * (1.0f / Cv);
    float var = sm2[0] * (1.0f / Cv) - mean * mean;
    float rstd = rsqrtf(var + 1e-5f);
    float4 w4 = ((const float4*)w)[tid];
    float4 b4 = ((const float4*)b)[tid];
    float y0 = (v.x - mean) * rstd * w4.x + b4.x;
    float y1 = (v.y - mean) * rstd * w4.y + b4.y;
    float y2 = (v.z - mean) * rstd * w4.z + b4.z;
    float y3 = (v.w - mean) * rstd * w4.w + b4.w;
    OT* op = out + (size_t)blockIdx.x * out_stride + tid * 4;
    if (sizeof(OT) == 2) {
        __half2* hp = (__half2*)op;
        hp[0] = __floats2half2_rn(y0, y1);
        hp[1] = __floats2half2_rn(y2, y3);
    } else {
        float4* fp = (float4*)op;
        *fp = make_float4(y0, y1, y2, y3);
    }
}

// ---------------------------------------------------------------------------
// Dense HGEMM: out[M,N] = A[M,K] @ W[N,K]^T + bias.  BMT x 128 tile, BK=64,
// 256 threads, 8 warps (4m x 2n), warp tile (BMT/4) x 64.
// EPI 0: half out.  1: fp32 residual in-place.  2: gelu half out.
// ---------------------------------------------------------------------------
#define BN 128
#define BKH 64

template <int EPI, int BMT>
__global__ __launch_bounds__(256) void hgemm_kernel(
    const __half* __restrict__ A, const __half* __restrict__ W,
    const float* __restrict__ bias, float* __restrict__ resio,
    __half* __restrict__ outh, int M, int N, int K) {
    constexpr int MT = BMT / 64;  // m16 tiles per warp
    extern __shared__ __align__(16) __half smx[];
    __half* As = smx;                  // 2 * BMT*64
    __half* Bs = smx + 2 * BMT * BKH;  // 2 * 128*64
    const int tid = threadIdx.x;
    const int lane = tid & 31;
    const int w = tid >> 5;
    const int wm = w >> 1;
    const int wn = w & 1;

    const __half* Ab = A + (size_t)(blockIdx.y * BMT) * K;
    const __half* Wb = W + (size_t)(blockIdx.x * BN) * K;
    uint32_t sA = cvta_s(As);
    uint32_t sB = cvta_s(Bs);

    float acc[MT][8][4];
#pragma unroll
    for (int i = 0; i < MT; i++)
#pragma unroll
        for (int j = 0; j < 8; j++)
#pragma unroll
            for (int q = 0; q < 4; q++) acc[i][j][q] = 0.f;

    const int KT = K / BKH;

    {
#pragma unroll
        for (int i = 0; i < BMT / 32; i++) {
            int g = tid + i * 256; int r = g >> 3; int c = g & 7;
            cp_async16(sA + sw(r, c * 8) * 2, Ab + (size_t)r * K + c * 8);
        }
#pragma unroll
        for (int i = 0; i < 4; i++) {
            int g = tid + i * 256; int r = g >> 3; int c = g & 7;
            cp_async16(sB + sw(r, c * 8) * 2, Wb + (size_t)r * K + c * 8);
        }
        cp_commit();
    }

    for (int kt = 0; kt < KT; ++kt) {
        int cur = kt & 1;
        if (kt + 1 < KT) {
            int nxt = cur ^ 1;
            int koff = (kt + 1) * BKH;
#pragma unroll
            for (int i = 0; i < BMT / 32; i++) {
                int g = tid + i * 256; int r = g >> 3; int c = g & 7;
                cp_async16(sA + (nxt * BMT * BKH + sw(r, c * 8)) * 2,
                           Ab + (size_t)r * K + koff + c * 8);
            }
#pragma unroll
            for (int i = 0; i < 4; i++) {
                int g = tid + i * 256; int r = g >> 3; int c = g & 7;
                cp_async16(sB + (nxt * BN * BKH + sw(r, c * 8)) * 2,
                           Wb + (size_t)r * K + koff + c * 8);
            }
            cp_commit();
            cp_wait<1>();
        } else {
            cp_wait<0>();
        }
        __syncthreads();

        uint32_t aB = sA + (uint32_t)(cur * BMT * BKH * 2);
        uint32_t bB = sB + (uint32_t)(cur * BN * BKH * 2);
#pragma unroll
        for (int ks = 0; ks < 4; ++ks) {
            int k0 = ks * 16;
            uint32_t af[MT][4];
#pragma unroll
            for (int mt = 0; mt < MT; ++mt) {
                int r = wm * (MT * 16) + mt * 16 + ((lane >> 3) & 1) * 8 + (lane & 7);
                int kc = k0 + ((lane >> 4) << 3);
                ldsm_x4(af[mt][0], af[mt][1], af[mt][2], af[mt][3],
                        aB + sw(r, kc) * 2);
            }
            uint32_t bf[8][2];
#pragma unroll
            for (int nt = 0; nt < 8; ++nt) {
                int l = lane & 15;
                int r = wn * 64 + nt * 8 + (l & 7);
                int kc = k0 + ((l >> 3) << 3);
                ldsm_x2(bf[nt][0], bf[nt][1], bB + sw(r, kc) * 2);
            }
#pragma unroll
            for (int mt = 0; mt < MT; ++mt)
#pragma unroll
                for (int nt = 0; nt < 8; ++nt)
                    mma16816(acc[mt][nt], af[mt][0], af[mt][1], af[mt][2],
                             af[mt][3], bf[nt][0], bf[nt][1]);
        }
        __syncthreads();
    }

    int g = lane >> 2, t = lane & 3;
#pragma unroll
    for (int mt = 0; mt < MT; ++mt) {
        int r0 = blockIdx.y * BMT + wm * (MT * 16) + mt * 16 + g;
#pragma unroll
        for (int nt = 0; nt < 8; ++nt) {
            int col = blockIdx.x * BN + wn * 64 + nt * 8 + 2 * t;
            float b0 = bias[col], b1 = bias[col + 1];
            float d0 = acc[mt][nt][0] + b0, d1 = acc[mt][nt][1] + b1;
            float d2 = acc[mt][nt][2] + b0, d3 = acc[mt][nt][3] + b1;
            if (EPI == 0) {
                *(__half2*)&outh[(size_t)r0 * N + col] = __floats2half2_rn(d0, d1);
                *(__half2*)&outh[(size_t)(r0 + 8) * N + col] = __floats2half2_rn(d2, d3);
            } else if (EPI == 1) {
                float2* p0 = (float2*)&resio[(size_t)r0 * N + col];
                float2 v0 = *p0; v0.x += d0; v0.y += d1; *p0 = v0;
                float2* p1 = (float2*)&resio[(size_t)(r0 + 8) * N + col];
                float2 v1 = *p1; v1.x += d2; v1.y += d3; *p1 = v1;
            } else {
                *(__half2*)&outh[(size_t)r0 * N + col] =
                    __floats2half2_rn(gelu_f(d0), gelu_f(d1));
                *(__half2*)&outh[(size_t)(r0 + 8) * N + col] =
                    __floats2half2_rn(gelu_f(d2), gelu_f(d3));
            }
        }
    }
}

// ---------------------------------------------------------------------------
// Fused flash attention (unmasked). Per CTA: 64 q rows of one (b,h).
// 128 threads = 4 warps, warp tile 16 q rows. j loop in tiles of 128,
// K/V double-buffered. Online softmax in fp32, P in fp16 regs.
// ---------------------------------------------------------------------------
#define FBR 64
#define FBC 128
#define FJT (Tv / FBC)  // 8

__global__ __launch_bounds__(128, 2) void flash_kernel(
    const __half* __restrict__ qkv, __half* __restrict__ o) {
    extern __shared__ __align__(16) __half fsm[];
    __half* Qs = fsm;                 // 64*64
    __half* Ks = fsm + FBR * HDv;     // 2 * 128*64
    __half* Vs = Ks + 2 * FBC * HDv;  // 2 * 128*64
    const uint32_t sQ = cvta_s(Qs), sK = cvta_s(Ks), sV = cvta_s(Vs);
    const int tid = threadIdx.x;
    const int lane = tid & 31;
    const int w = tid >> 5;

    const int z = blockIdx.y, b = z >> 4, h = z & 15;
    const int i0 = blockIdx.x * FBR;
    const __half* qb = qkv + ((size_t)(b * Tv + i0)) * KQKV + h * HDv;
    const __half* kb = qkv + ((size_t)b * Tv) * KQKV + Cv + h * HDv;
    const __half* vb = kb + Cv;

    // prologue: Q + K0 + V0
#pragma unroll
    for (int i = 0; i < 4; i++) {
        int g = tid + i * 128; int r = g >> 3; int c = g & 7;
        cp_async16(sQ + sw(r, c * 8) * 2, qb + (size_t)r * KQKV + c * 8);
    }
#pragma unroll
    for (int i = 0; i < 8; i++) {
        int g = tid + i * 128; int r = g >> 3; int c = g & 7;
        cp_async16(sK + sw(r, c * 8) * 2, kb + (size_t)r * KQKV + c * 8);
        cp_async16(sV + sw(r, c * 8) * 2, vb + (size_t)r * KQKV + c * 8);
    }
    cp_commit();

    float m0 = -1e30f, m1 = -1e30f, s0 = 0.f, s1 = 0.f;
    float acc_o[8][4];
#pragma unroll
    for (int i = 0; i < 8; i++)
#pragma unroll
        for (int q = 0; q < 4; q++) acc_o[i][q] = 0.f;

    uint32_t qf[4][4];

    for (int jt = 0; jt < FJT; ++jt) {
        int cur = jt & 1;
        if (jt + 1 < FJT) {
            int nxt = cur ^ 1;
            int j0n = (jt + 1) * FBC;
#pragma unroll
            for (int i = 0; i < 8; i++) {
                int g = tid + i * 128; int r = g >> 3; int c = g & 7;
                cp_async16(sK + (nxt * FBC * HDv + sw(r, c * 8)) * 2,
                           kb + (size_t)(j0n + r) * KQKV + c * 8);
                cp_async16(sV + (nxt * FBC * HDv + sw(r, c * 8)) * 2,
                           vb + (size_t)(j0n + r) * KQKV + c * 8);
            }
            cp_commit();
            cp_wait<1>();
        } else {
            cp_wait<0>();
        }
        __syncthreads();

        if (jt == 0) {
#pragma unroll
            for (int ks = 0; ks < 4; ++ks) {
                int r = w * 16 + ((lane >> 3) & 1) * 8 + (lane & 7);
                int kc = ks * 16 + ((lane >> 4) << 3);
                ldsm_x4(qf[ks][0], qf[ks][1], qf[ks][2], qf[ks][3],
                        sQ + sw(r, kc) * 2);
            }
        }

        uint32_t kB = sK + (uint32_t)(cur * FBC * HDv * 2);
        uint32_t vB = sV + (uint32_t)(cur * FBC * HDv * 2);

        // S = Q K^T (16 x 128 per warp)
        float acc_s[16][4];
#pragma unroll
        for (int i = 0; i < 16; i++)
#pragma unroll
            for (int q = 0; q < 4; q++) acc_s[i][q] = 0.f;

#pragma unroll
        for (int ks = 0; ks < 4; ++ks) {
            int k0 = ks * 16;
#pragma unroll
            for (int ntp = 0; ntp < 8; ++ntp) {
                uint32_t b0, b1, b2, b3;
                int r = ntp * 16 + (lane >> 4) * 8 + (lane & 7);
                int kc = k0 + ((lane >> 3) & 1) * 8;
                ldsm_x4(b0, b1, b2, b3, kB + sw(r, kc) * 2);
                mma16816(acc_s[2 * ntp], qf[ks][0], qf[ks][1], qf[ks][2],
                         qf[ks][3], b0, b1);
                mma16816(acc_s[2 * ntp + 1], qf[ks][0], qf[ks][1], qf[ks][2],
                         qf[ks][3], b2, b3);
            }
        }

        // scale + online softmax
        float m0n = m0, m1n = m1;
#pragma unroll
        for (int nt = 0; nt < 16; ++nt) {
            acc_s[nt][0] *= 0.125f; acc_s[nt][1] *= 0.125f;
            acc_s[nt][2] *= 0.125f; acc_s[nt][3] *= 0.125f;
            m0n = fmaxf(m0n, fmaxf(acc_s[nt][0], acc_s[nt][1]));
            m1n = fmaxf(m1n, fmaxf(acc_s[nt][2], acc_s[nt][3]));
        }
#pragma unroll
        for (int off = 1; off <= 2; off <<= 1) {
            m0n = fmaxf(m0n, __shfl_xor_sync(0xffffffffu, m0n, off));
            m1n = fmaxf(m1n, __shfl_xor_sync(0xffffffffu, m1n, off));
        }
        float alpha0 = __expf(m0 - m0n);
        float alpha1 = __expf(m1 - m1n);
        m0 = m0n; m1 = m1n;

        float r0 = 0.f, r1 = 0.f;
#pragma unroll
        for (int nt = 0; nt < 16; ++nt) {
            acc_s[nt][0] = __expf(acc_s[nt][0] - m0n);
            acc_s[nt][1] = __expf(acc_s[nt][1] - m0n);
            acc_s[nt][2] = __expf(acc_s[nt][2] - m1n);
            acc_s[nt][3] = __expf(acc_s[nt][3] - m1n);
            r0 += acc_s[nt][0] + acc_s[nt][1];
            r1 += acc_s[nt][2] + acc_s[nt][3];
        }
#pragma unroll
        for (int off = 1; off <= 2; off <<= 1) {
            r0 += __shfl_xor_sync(0xffffffffu, r0, off);
            r1 += __shfl_xor_sync(0xffffffffu, r1, off);
        }
        s0 = s0 * alpha0 + r0;
        s1 = s1 * alpha1 + r1;

#pragma unroll
        for (int nt = 0; nt < 8; ++nt) {
            acc_o[nt][0] *= alpha0; acc_o[nt][1] *= alpha0;
            acc_o[nt][2] *= alpha1; acc_o[nt][3] *= alpha1;
        }

        // O += P V  (k over 128 j's, 8 chunks of 16)
#pragma unroll
        for (int kc = 0; kc < 8; ++kc) {
            uint32_t a0 = pack_half2(acc_s[2 * kc][0], acc_s[2 * kc][1]);
            uint32_t a1 = pack_half2(acc_s[2 * kc][2], acc_s[2 * kc][3]);
            uint32_t a2 = pack_half2(acc_s[2 * kc + 1][0], acc_s[2 * kc + 1][1]);
            uint32_t a3 = pack_half2(acc_s[2 * kc + 1][2], acc_s[2 * kc + 1][3]);
#pragma unroll
            for (int dp = 0; dp < 4; ++dp) {
                uint32_t b0, b1, b2, b3;
                int r = kc * 16 + ((lane >> 3) & 1) * 8 + (lane & 7);
                int c = dp * 16 + (lane >> 4) * 8;
                ldsm_x4t(b0, b1, b2, b3, vB + sw(r, c) * 2);
                mma16816(acc_o[2 * dp], a0, a1, a2, a3, b0, b1);
                mma16816(acc_o[2 * dp + 1], a0, a1, a2, a3, b2, b3);
            }
        }
        __syncthreads();
    }

    // epilogue
    float inv0 = 1.0f / s0, inv1 = 1.0f / s1;
    int g = lane >> 2, t = lane & 3;
    int ro0 = i0 + w * 16 + g;
#pragma unroll
    for (int nt = 0; nt < 8; ++nt) {
        int d = nt * 8 + 2 * t;
        *(__half2*)&o[((size_t)b * Tv + ro0) * Cv + h * HDv + d] =
            __floats2half2_rn(acc_o[nt][0] * inv0, acc_o[nt][1] * inv0);
        *(__half2*)&o[((size_t)b * Tv + ro0 + 8) * Cv + h * HDv + d] =
            __floats2half2_rn(acc_o[nt][2] * inv1, acc_o[nt][3] * inv1);
    }
}

// ---------------------------------------------------------------------------
__global__ void logits_kernel(const float* __restrict__ xf,
                              const float* __restrict__ wte,
                              float* __restrict__ out) {
    int warp = (blockIdx.x * blockDim.x + threadIdx.x) >> 5;
    int lane = threadIdx.x & 31;
    if (warp >= Vv) return;
    const float4* w4 = (const float4*)(wte + (size_t)warp * Cv);
    const float4* x0 = (const float4*)xf;
    const float4* x1 = (const float4*)(xf + Cv);
    float s0 = 0.f, s1 = 0.f;
#pragma unroll
    for (int i = lane; i < Cv / 4; i += 32) {
        float4 w = w4[i];
        float4 a = x0[i];
        float4 c = x1[i];
        s0 += w.x * a.x + w.y * a.y + w.z * a.z + w.w * a.w;
        s1 += w.x * c.x + w.y * c.y + w.z * c.z + w.w * c.w;
    }
#pragma unroll
    for (int o = 16; o > 0; o >>= 1) {
        s0 += __shfl_down_sync(0xffffffffu, s0, o);
        s1 += __shfl_down_sync(0xffffffffu, s1, o);
    }
    if (lane == 0) {
        out[warp] = s0;
        out[Vv + warp] = s1;
    }
}

// ---------------------------------------------------------------------------
extern "C" void kernel_launch(void* const* d_in, const int* in_sizes, int n_in,
                              void* d_out, int out_size) {
    const int* idx = (const int*)d_in[0];
    const float* wte = (const float*)d_in[1];
    const float* wpe = (const float*)d_in[2];
    const float* ln1_w = (const float*)d_in[3];
    const float* ln1_b = (const float*)d_in[4];
    const float* attn_w = (const float*)d_in[5];
    const float* attn_b = (const float*)d_in[6];
    const float* proj_w = (const float*)d_in[7];
    const float* proj_b = (const float*)d_in[8];
    const float* ln2_w = (const float*)d_in[9];
    const float* ln2_b = (const float*)d_in[10];
    const float* fc_w = (const float*)d_in[11];
    const float* fc_b = (const float*)d_in[12];
    const float* fc2_w = (const float*)d_in[13];
    const float* fc2_b = (const float*)d_in[14];
    const float* lnf_w = (const float*)d_in[15];
    const float* lnf_b = (const float*)d_in[16];
    float* out = (float*)d_out;

    float* x;    cudaGetSymbolAddress((void**)&x, g_x);
    __half* ln;  cudaGetSymbolAddress((void**)&ln, g_ln);
    __half* qkv; cudaGetSymbolAddress((void**)&qkv, g_qkv);
    __half* o;   cudaGetSymbolAddress((void**)&o, g_o);
    __half* fc;  cudaGetSymbolAddress((void**)&fc, g_fc);
    float* xf;   cudaGetSymbolAddress((void**)&xf, g_xf);
    __half* wa;  cudaGetSymbolAddress((void**)&wa, g_wa);
    __half* wp;  cudaGetSymbolAddress((void**)&wp, g_wp);
    __half* wf;  cudaGetSymbolAddress((void**)&wf, g_wf);
    __half* wf2; cudaGetSymbolAddress((void**)&wf2, g_wf2);

    const int HSM256 = 2 * (256 * BKH + BN * BKH) * 2;  // 98304
    const int HSM128 = 2 * (128 * BKH + BN * BKH) * 2;  // 65536
    const int FSM = (FBR * HDv + 4 * FBC * HDv) * 2;    // 73728
    cudaFuncSetAttribute(hgemm_kernel<0, 256>, cudaFuncAttributeMaxDynamicSharedMemorySize, HSM256);
    cudaFuncSetAttribute(hgemm_kernel<2, 256>, cudaFuncAttributeMaxDynamicSharedMemorySize, HSM256);
    cudaFuncSetAttribute(hgemm_kernel<1, 128>, cudaFuncAttributeMaxDynamicSharedMemorySize, HSM128);
    cudaFuncSetAttribute(flash_kernel, cudaFuncAttributeMaxDynamicSharedMemorySize, FSM);

    {
        int n4a = Lv * 3 * Cv * Cv / 4;
        f2h_kernel<<<(n4a + 255) / 256, 256>>>(attn_w, wa, n4a);
        int n4p = Lv * Cv * Cv / 4;
        f2h_kernel<<<(n4p + 255) / 256, 256>>>(proj_w, wp, n4p);
        int n4f = Lv * 4 * Cv * Cv / 4;
        f2h_kernel<<<(n4f + 255) / 256, 256>>>(fc_w, wf, n4f);
        f2h_kernel<<<(n4f + 255) / 256, 256>>>(fc2_w, wf2, n4f);
    }

    embed_kernel<<<BTv, 256>>>(idx, wte, wpe, x);

    for (int l = 0; l < Lv; ++l) {
        layernorm_kernel<__half><<<BTv, 256>>>(x, Cv, ln1_w + l * Cv, ln1_b + l * Cv, ln, Cv);
        hgemm_kernel<0, 256><<<dim3(3 * Cv / BN, BTv / 256), 256, HSM256>>>(
            ln, wa + (size_t)l * 3 * Cv * Cv, attn_b + l * 3 * Cv, nullptr, qkv,
            BTv, 3 * Cv, Cv);
        flash_kernel<<<dim3(Tv / FBR, Bv * Hv), 128, FSM>>>(qkv, o);
        hgemm_kernel<1, 128><<<dim3(Cv / BN, BTv / 128), 256, HSM128>>>(
            o, wp + (size_t)l * Cv * Cv, proj_b + l * Cv, x, nullptr, BTv, Cv, Cv);
        layernorm_kernel<__half><<<BTv, 256>>>(x, Cv, ln2_w + l * Cv, ln2_b + l * Cv, ln, Cv);
        hgemm_kernel<2, 256><<<dim3(4 * Cv / BN, BTv / 256), 256, HSM256>>>(
            ln, wf + (size_t)l * 4 * Cv * Cv, fc_b + l * 4 * Cv, nullptr, fc, BTv,
            4 * Cv, Cv);
        hgemm_kernel<1, 128><<<dim3(Cv / BN, BTv / 128), 256, HSM128>>>(
            fc, wf2 + (size_t)l * 4 * Cv * Cv, fc2_b + l * Cv, x, nullptr, BTv, Cv,
            4 * Cv);
    }

    layernorm_kernel<float><<<Bv, 256>>>(x + (size_t)(Tv - 1) * Cv, (size_t)Tv * Cv,
                                         lnf_w, lnf_b, xf, Cv);
    int blocks = (Vv * 32 + 255) / 256;
    logits_kernel<<<blocks, 256>>>(xf, wte, out);
}

// round 6
// speedup vs baseline: 7.9378x; 1.0026x over previous
#include <cuda_runtime.h>
#include <cuda_fp16.h>
#include <math.h>
#include <stdint.h>

// ---------------------------------------------------------------------------
// GPT forward. fp16 mma.sync tensor cores, 3-stage pipelined GEMM,
// fused flash attention. tcgen05 is unavailable (harness targets sm_103).
// B=2, T=1024, C=1024, L=4, H=16, HD=64, V=50257. Unmasked attention.
// ---------------------------------------------------------------------------

#define Bv 2
#define Tv 1024
#define Cv 1024
#define Lv 4
#define Hv 16
#define HDv 64
#define Vv 50257
#define BTv 2048
#define KQKV (3 * Cv)

// ---- scratch ---------------------------------------------------------------
__device__ float  g_x[BTv * Cv];
__device__ __half g_ln[BTv * Cv];
__device__ __half g_qkv[BTv * 3 * Cv];
__device__ __half g_o[BTv * Cv];
__device__ __half g_fc[BTv * 4 * Cv];
__device__ float  g_xf[Bv * Cv];
__device__ __half g_wa[Lv * 3 * Cv * Cv];
__device__ __half g_wp[Lv * Cv * Cv];
__device__ __half g_wf[Lv * 4 * Cv * Cv];
__device__ __half g_wf2[Lv * 4 * Cv * Cv];

// ---- PTX helpers ------------------------------------------------------------
__device__ __forceinline__ uint32_t cvta_s(const void* p) {
    return (uint32_t)__cvta_generic_to_shared(p);
}
__device__ __forceinline__ void cp_async16(uint32_t s, const void* g) {
    asm volatile("cp.async.cg.shared.global [%0], [%1], 16;" ::"r"(s), "l"(g));
}
__device__ __forceinline__ void cp_commit() {
    asm volatile("cp.async.commit_group;");
}
template <int N>
__device__ __forceinline__ void cp_wait() {
    asm volatile("cp.async.wait_group %0;" ::"n"(N));
}
__device__ __forceinline__ void ldsm_x4(uint32_t& r0, uint32_t& r1, uint32_t& r2,
                                        uint32_t& r3, uint32_t a) {
    asm volatile("ldmatrix.sync.aligned.m8n8.x4.shared.b16 {%0,%1,%2,%3}, [%4];"
                 : "=r"(r0), "=r"(r1), "=r"(r2), "=r"(r3) : "r"(a));
}
__device__ __forceinline__ void ldsm_x4t(uint32_t& r0, uint32_t& r1, uint32_t& r2,
                                         uint32_t& r3, uint32_t a) {
    asm volatile("ldmatrix.sync.aligned.m8n8.x4.trans.shared.b16 {%0,%1,%2,%3}, [%4];"
                 : "=r"(r0), "=r"(r1), "=r"(r2), "=r"(r3) : "r"(a));
}
__device__ __forceinline__ void mma16816(float* c, uint32_t a0, uint32_t a1,
                                         uint32_t a2, uint32_t a3, uint32_t b0,
                                         uint32_t b1) {
    asm volatile(
        "mma.sync.aligned.m16n8k16.row.col.f32.f16.f16.f32 "
        "{%0,%1,%2,%3}, {%4,%5,%6,%7}, {%8,%9}, {%0,%1,%2,%3};"
        : "+f"(c[0]), "+f"(c[1]), "+f"(c[2]), "+f"(c[3])
        : "r"(a0), "r"(a1), "r"(a2), "r"(a3), "r"(b0), "r"(b1));
}
__device__ __forceinline__ uint32_t pack_half2(float a, float b) {
    __half2 h = __floats2half2_rn(a, b);
    return *reinterpret_cast<uint32_t*>(&h);
}
// swizzled half-offset; tile row = 64 halves (8 x 16B chunks)
__device__ __forceinline__ uint32_t sw(int row, int kcol) {
    return (uint32_t)((row << 6) + ((((kcol >> 3) ^ (row & 7)) << 3) + (kcol & 7)));
}
__device__ __forceinline__ float gelu_f(float x) {
    return 0.5f * x * (1.0f + erff(x * 0.70710678118654752f));
}

// ---------------------------------------------------------------------------
// fused fp32->fp16 weight conversion for all 4 weight groups (one launch)
// sizes in float4 units: wa 3M, wp 1M, wf 4M, wf2 4M
// ---------------------------------------------------------------------------
#define N4A (Lv * 3 * Cv * Cv / 4)
#define N4P (Lv * Cv * Cv / 4)
#define N4F (Lv * 4 * Cv * Cv / 4)

__global__ void f2h_all_kernel(const float* __restrict__ sa, __half* __restrict__ da,
                               const float* __restrict__ sp, __half* __restrict__ dp,
                               const float* __restrict__ sf, __half* __restrict__ df,
                               const float* __restrict__ sf2, __half* __restrict__ df2) {
    int i = blockIdx.x * blockDim.x + threadIdx.x;
    const float* s;
    __half* d;
    if (i < N4A) {
        s = sa; d = da;
    } else if (i < N4A + N4P) {
        i -= N4A; s = sp; d = dp;
    } else if (i < N4A + N4P + N4F) {
        i -= N4A + N4P; s = sf; d = df;
    } else {
        i -= N4A + N4P + N4F; s = sf2; d = df2;
        if (i >= N4F) return;
    }
    float4 v = ((const float4*)s)[i];
    __half2* o = (__half2*)(d + (size_t)i * 4);
    o[0] = __floats2half2_rn(v.x, v.y);
    o[1] = __floats2half2_rn(v.z, v.w);
}

__global__ void embed_kernel(const int* __restrict__ idx,
                             const float* __restrict__ wte,
                             const float* __restrict__ wpe,
                             float* __restrict__ x) {
    int row = blockIdx.x;
    int t = row & (Tv - 1);
    int tok = idx[row];
    float4 va = ((const float4*)(wte + (size_t)tok * Cv))[threadIdx.x];
    float4 vp = ((const float4*)(wpe + (size_t)t * Cv))[threadIdx.x];
    ((float4*)(x + (size_t)row * Cv))[threadIdx.x] =
        make_float4(va.x + vp.x, va.y + vp.y, va.z + vp.z, va.w + vp.w);
}

// ---------------------------------------------------------------------------
template <typename OT>
__global__ void layernorm_kernel(const float* __restrict__ in, size_t in_stride,
                                 const float* __restrict__ w,
                                 const float* __restrict__ b,
                                 OT* __restrict__ out, size_t out_stride) {
    const float* p = in + (size_t)blockIdx.x * in_stride;
    int tid = threadIdx.x;
    float4 v = ((const float4*)p)[tid];
    float s = v.x + v.y + v.z + v.w;
    float ss = v.x * v.x + v.y * v.y + v.z * v.z + v.w * v.w;

    __shared__ float sm1[8], sm2[8];
    int lane = tid & 31, wid = tid >> 5;
#pragma unroll
    for (int o = 16; o > 0; o >>= 1) {
        s += __shfl_down_sync(0xffffffffu, s, o);
        ss += __shfl_down_sync(0xffffffffu, ss, o);
    }
    if (lane == 0) { sm1[wid] = s; sm2[wid] = ss; }
    __syncthreads();
    if (wid == 0) {
        s = (lane < 8) ? sm1[lane] : 0.f;
        ss = (lane < 8) ? sm2[lane] : 0.f;
#pragma unroll
        for (int o = 4; o > 0; o >>= 1) {
            s += __shfl_down_sync(0xffffffffu, s, o);
            ss += __shfl_down_sync(0xffffffffu, ss, o);
        }
        if (lane == 0) { sm1[0] = s; sm2[0] = ss; }
    }
    __syncthreads();
    float mean = sm1[0] * (1.0f / Cv);
    float var = sm2[0] * (1.0f / Cv) - mean * mean;
    float rstd = rsqrtf(var + 1e-5f);
    float4 w4 = ((const float4*)w)[tid];
    float4 b4 = ((const float4*)b)[tid];
    float y0 = (v.x - mean) * rstd * w4.x + b4.x;
    float y1 = (v.y - mean) * rstd * w4.y + b4.y;
    float y2 = (v.z - mean) * rstd * w4.z + b4.z;
    float y3 = (v.w - mean) * rstd * w4.w + b4.w;
    OT* op = out + (size_t)blockIdx.x * out_stride + tid * 4;
    if (sizeof(OT) == 2) {
        __half2* hp = (__half2*)op;
        hp[0] = __floats2half2_rn(y0, y1);
        hp[1] = __floats2half2_rn(y2, y3);
    } else {
        float4* fp = (float4*)op;
        *fp = make_float4(y0, y1, y2, y3);
    }
}

// ---------------------------------------------------------------------------
// Dense HGEMM: out[M,N] = A[M,K](half) @ W[N,K](half)^T + bias.
// CTA tile BMT x 128, BK=64, 3-stage cp.async pipeline, ONE barrier per stage.
// 256 threads, 8 warps (4m x 2n), warp tile (BMT/4) x 64.
// EPI 0: half out. 1: fp32 residual in-place. 2: gelu half out.
// ---------------------------------------------------------------------------
#define BN 128
#define BKH 64

template <int EPI, int BMT>
__global__ __launch_bounds__(256, (BMT == 64) ? 2 : 1) void hgemm_kernel(
    const __half* __restrict__ A, const __half* __restrict__ W,
    const float* __restrict__ bias, float* __restrict__ resio,
    __half* __restrict__ outh, int M, int N, int K) {
    constexpr int S = 3;                 // pipeline stages
    constexpr int MT = BMT / 64;         // m16 tiles per warp
    constexpr int ASTG = BMT * BKH;      // halves per A stage
    constexpr int BSTG = BN * BKH;       // halves per B stage
    extern __shared__ __align__(16) __half smx[];
    __half* As = smx;              // S * ASTG
    __half* Bs = smx + S * ASTG;   // S * BSTG
    const int tid = threadIdx.x;
    const int lane = tid & 31;
    const int w = tid >> 5;
    const int wm = w >> 1;
    const int wn = w & 1;

    const __half* Ab = A + (size_t)(blockIdx.y * BMT) * K;
    const __half* Wb = W + (size_t)(blockIdx.x * BN) * K;
    uint32_t sA = cvta_s(As);
    uint32_t sB = cvta_s(Bs);

    float acc[MT][8][4];
#pragma unroll
    for (int i = 0; i < MT; i++)
#pragma unroll
        for (int j = 0; j < 8; j++)
#pragma unroll
            for (int q = 0; q < 4; q++) acc[i][j][q] = 0.f;

    const int KT = K / BKH;

    auto load_stage = [&](int kt) {
        int stg = kt % S;
        int koff = kt * BKH;
        uint32_t dA = sA + stg * ASTG * 2;
        uint32_t dB = sB + stg * BSTG * 2;
#pragma unroll
        for (int i = 0; i < BMT / 32; i++) {
            int g = tid + i * 256; int r = g >> 3; int c = g & 7;
            cp_async16(dA + sw(r, c * 8) * 2, Ab + (size_t)r * K + koff + c * 8);
        }
#pragma unroll
        for (int i = 0; i < BN / 32; i++) {
            int g = tid + i * 256; int r = g >> 3; int c = g & 7;
            cp_async16(dB + sw(r, c * 8) * 2, Wb + (size_t)r * K + koff + c * 8);
        }
        cp_commit();
    };

    load_stage(0);
    load_stage(1);

    for (int kt = 0; kt < KT; ++kt) {
        if (kt == KT - 1) cp_wait<0>(); else cp_wait<1>();
        __syncthreads();
        if (kt + 2 < KT) load_stage(kt + 2);

        int stg = kt % S;
        uint32_t aB = sA + (uint32_t)(stg * ASTG * 2);
        uint32_t bB = sB + (uint32_t)(stg * BSTG * 2);
#pragma unroll
        for (int ks = 0; ks < 4; ++ks) {
            int k0 = ks * 16;
            uint32_t af[MT][4];
#pragma unroll
            for (int mt = 0; mt < MT; ++mt) {
                int r = wm * (MT * 16) + mt * 16 + ((lane >> 3) & 1) * 8 + (lane & 7);
                int kc = k0 + ((lane >> 4) << 3);
                ldsm_x4(af[mt][0], af[mt][1], af[mt][2], af[mt][3],
                        aB + sw(r, kc) * 2);
            }
            // B fragments: one x4 covers two n-tiles (16 rows)
            uint32_t bf[4][4];
#pragma unroll
            for (int np = 0; np < 4; ++np) {
                int r = wn * 64 + np * 16 + (lane & 7) + (((lane >> 4) & 1) << 3);
                int kc = k0 + (((lane >> 3) & 1) << 3);
                ldsm_x4(bf[np][0], bf[np][1], bf[np][2], bf[np][3],
                        bB + sw(r, kc) * 2);
            }
#pragma unroll
            for (int mt = 0; mt < MT; ++mt)
#pragma unroll
                for (int np = 0; np < 4; ++np) {
                    mma16816(acc[mt][2 * np], af[mt][0], af[mt][1], af[mt][2],
                             af[mt][3], bf[np][0], bf[np][1]);
                    mma16816(acc[mt][2 * np + 1], af[mt][0], af[mt][1], af[mt][2],
                             af[mt][3], bf[np][2], bf[np][3]);
                }
        }
    }

    int g = lane >> 2, t = lane & 3;
#pragma unroll
    for (int mt = 0; mt < MT; ++mt) {
        int r0 = blockIdx.y * BMT + wm * (MT * 16) + mt * 16 + g;
#pragma unroll
        for (int nt = 0; nt < 8; ++nt) {
            int col = blockIdx.x * BN + wn * 64 + nt * 8 + 2 * t;
            float b0 = bias[col], b1 = bias[col + 1];
            float d0 = acc[mt][nt][0] + b0, d1 = acc[mt][nt][1] + b1;
            float d2 = acc[mt][nt][2] + b0, d3 = acc[mt][nt][3] + b1;
            if (EPI == 0) {
                *(__half2*)&outh[(size_t)r0 * N + col] = __floats2half2_rn(d0, d1);
                *(__half2*)&outh[(size_t)(r0 + 8) * N + col] = __floats2half2_rn(d2, d3);
            } else if (EPI == 1) {
                float2* p0 = (float2*)&resio[(size_t)r0 * N + col];
                float2 v0 = *p0; v0.x += d0; v0.y += d1; *p0 = v0;
                float2* p1 = (float2*)&resio[(size_t)(r0 + 8) * N + col];
                float2 v1 = *p1; v1.x += d2; v1.y += d3; *p1 = v1;
            } else {
                *(__half2*)&outh[(size_t)r0 * N + col] =
                    __floats2half2_rn(gelu_f(d0), gelu_f(d1));
                *(__half2*)&outh[(size_t)(r0 + 8) * N + col] =
                    __floats2half2_rn(gelu_f(d2), gelu_f(d3));
            }
        }
    }
}

// ---------------------------------------------------------------------------
// Fused flash attention (unmasked). Per CTA: 64 q rows of one (b,h).
// 128 threads = 4 warps, warp tile 16 q rows. j loop in tiles of 128,
// K/V double-buffered, ONE barrier per j-tile.
// ---------------------------------------------------------------------------
#define FBR 64
#define FBC 128
#define FJT (Tv / FBC)  // 8

__global__ __launch_bounds__(128, 2) void flash_kernel(
    const __half* __restrict__ qkv, __half* __restrict__ o) {
    extern __shared__ __align__(16) __half fsm[];
    __half* Qs = fsm;
    __half* Ks = fsm + FBR * HDv;
    __half* Vs = Ks + 2 * FBC * HDv;
    const uint32_t sQ = cvta_s(Qs), sK = cvta_s(Ks), sV = cvta_s(Vs);
    const int tid = threadIdx.x;
    const int lane = tid & 31;
    const int w = tid >> 5;

    const int z = blockIdx.y, b = z >> 4, h = z & 15;
    const int i0 = blockIdx.x * FBR;
    const __half* qb = qkv + ((size_t)(b * Tv + i0)) * KQKV + h * HDv;
    const __half* kb = qkv + ((size_t)b * Tv) * KQKV + Cv + h * HDv;
    const __half* vb = kb + Cv;

    auto load_kv = [&](int jt) {
        int buf = jt & 1;
        int j0 = jt * FBC;
#pragma unroll
        for (int i = 0; i < 8; i++) {
            int g = tid + i * 128; int r = g >> 3; int c = g & 7;
            cp_async16(sK + (buf * FBC * HDv + sw(r, c * 8)) * 2,
                       kb + (size_t)(j0 + r) * KQKV + c * 8);
            cp_async16(sV + (buf * FBC * HDv + sw(r, c * 8)) * 2,
                       vb + (size_t)(j0 + r) * KQKV + c * 8);
        }
        cp_commit();
    };

    // prologue: Q + (K0,V0)
#pragma unroll
    for (int i = 0; i < 4; i++) {
        int g = tid + i * 128; int r = g >> 3; int c = g & 7;
        cp_async16(sQ + sw(r, c * 8) * 2, qb + (size_t)r * KQKV + c * 8);
    }
    load_kv(0);

    float m0 = -1e30f, m1 = -1e30f, s0 = 0.f, s1 = 0.f;
    float acc_o[8][4];
#pragma unroll
    for (int i = 0; i < 8; i++)
#pragma unroll
        for (int q = 0; q < 4; q++) acc_o[i][q] = 0.f;

    uint32_t qf[4][4];

    for (int jt = 0; jt < FJT; ++jt) {
        int cur = jt & 1;
        cp_wait<0>();
        __syncthreads();
        if (jt + 1 < FJT) load_kv(jt + 1);

        if (jt == 0) {
#pragma unroll
            for (int ks = 0; ks < 4; ++ks) {
                int r = w * 16 + ((lane >> 3) & 1) * 8 + (lane & 7);
                int kc = ks * 16 + ((lane >> 4) << 3);
                ldsm_x4(qf[ks][0], qf[ks][1], qf[ks][2], qf[ks][3],
                        sQ + sw(r, kc) * 2);
            }
        }

        uint32_t kB = sK + (uint32_t)(cur * FBC * HDv * 2);
        uint32_t vB = sV + (uint32_t)(cur * FBC * HDv * 2);

        float acc_s[16][4];
#pragma unroll
        for (int i = 0; i < 16; i++)
#pragma unroll
            for (int q = 0; q < 4; q++) acc_s[i][q] = 0.f;

#pragma unroll
        for (int ks = 0; ks < 4; ++ks) {
            int k0 = ks * 16;
#pragma unroll
            for (int ntp = 0; ntp < 8; ++ntp) {
                uint32_t b0, b1, b2, b3;
                int r = ntp * 16 + (lane >> 4) * 8 + (lane & 7);
                int kc = k0 + ((lane >> 3) & 1) * 8;
                ldsm_x4(b0, b1, b2, b3, kB + sw(r, kc) * 2);
                mma16816(acc_s[2 * ntp], qf[ks][0], qf[ks][1], qf[ks][2],
                         qf[ks][3], b0, b1);
                mma16816(acc_s[2 * ntp + 1], qf[ks][0], qf[ks][1], qf[ks][2],
                         qf[ks][3], b2, b3);
            }
        }

        float m0n = m0, m1n = m1;
#pragma unroll
        for (int nt = 0; nt < 16; ++nt) {
            acc_s[nt][0] *= 0.125f; acc_s[nt][1] *= 0.125f;
            acc_s[nt][2] *= 0.125f; acc_s[nt][3] *= 0.125f;
            m0n = fmaxf(m0n, fmaxf(acc_s[nt][0], acc_s[nt][1]));
            m1n = fmaxf(m1n, fmaxf(acc_s[nt][2], acc_s[nt][3]));
        }
#pragma unroll
        for (int off = 1; off <= 2; off <<= 1) {
            m0n = fmaxf(m0n, __shfl_xor_sync(0xffffffffu, m0n, off));
            m1n = fmaxf(m1n, __shfl_xor_sync(0xffffffffu, m1n, off));
        }
        float alpha0 = __expf(m0 - m0n);
        float alpha1 = __expf(m1 - m1n);
        m0 = m0n; m1 = m1n;

        float r0 = 0.f, r1 = 0.f;
#pragma unroll
        for (int nt = 0; nt < 16; ++nt) {
            acc_s[nt][0] = __expf(acc_s[nt][0] - m0n);
            acc_s[nt][1] = __expf(acc_s[nt][1] - m0n);
            acc_s[nt][2] = __expf(acc_s[nt][2] - m1n);
            acc_s[nt][3] = __expf(acc_s[nt][3] - m1n);
            r0 += acc_s[nt][0] + acc_s[nt][1];
            r1 += acc_s[nt][2] + acc_s[nt][3];
        }
#pragma unroll
        for (int off = 1; off <= 2; off <<= 1) {
            r0 += __shfl_xor_sync(0xffffffffu, r0, off);
            r1 += __shfl_xor_sync(0xffffffffu, r1, off);
        }
        s0 = s0 * alpha0 + r0;
        s1 = s1 * alpha1 + r1;

#pragma unroll
        for (int nt = 0; nt < 8; ++nt) {
            acc_o[nt][0] *= alpha0; acc_o[nt][1] *= alpha0;
            acc_o[nt][2] *= alpha1; acc_o[nt][3] *= alpha1;
        }

#pragma unroll
        for (int kc = 0; kc < 8; ++kc) {
            uint32_t a0 = pack_half2(acc_s[2 * kc][0], acc_s[2 * kc][1]);
            uint32_t a1 = pack_half2(acc_s[2 * kc][2], acc_s[2 * kc][3]);
            uint32_t a2 = pack_half2(acc_s[2 * kc + 1][0], acc_s[2 * kc + 1][1]);
            uint32_t a3 = pack_half2(acc_s[2 * kc + 1][2], acc_s[2 * kc + 1][3]);
#pragma unroll
            for (int dp = 0; dp < 4; ++dp) {
                uint32_t b0, b1, b2, b3;
                int r = kc * 16 + ((lane >> 3) & 1) * 8 + (lane & 7);
                int c = dp * 16 + (lane >> 4) * 8;
                ldsm_x4t(b0, b1, b2, b3, vB + sw(r, c) * 2);
                mma16816(acc_o[2 * dp], a0, a1, a2, a3, b0, b1);
                mma16816(acc_o[2 * dp + 1], a0, a1, a2, a3, b2, b3);
            }
        }
    }

    float inv0 = 1.0f / s0, inv1 = 1.0f / s1;
    int g = lane >> 2, t = lane & 3;
    int ro0 = i0 + w * 16 + g;
#pragma unroll
    for (int nt = 0; nt < 8; ++nt) {
        int d = nt * 8 + 2 * t;
        *(__half2*)&o[((size_t)b * Tv + ro0) * Cv + h * HDv + d] =
            __floats2half2_rn(acc_o[nt][0] * inv0, acc_o[nt][1] * inv0);
        *(__half2*)&o[((size_t)b * Tv + ro0 + 8) * Cv + h * HDv + d] =
            __floats2half2_rn(acc_o[nt][2] * inv1, acc_o[nt][3] * inv1);
    }
}

// ---------------------------------------------------------------------------
__global__ void logits_kernel(const float* __restrict__ xf,
                              const float* __restrict__ wte,
                              float* __restrict__ out) {
    int warp = (blockIdx.x * blockDim.x + threadIdx.x) >> 5;
    int lane = threadIdx.x & 31;
    if (warp >= Vv) return;
    const float4* w4 = (const float4*)(wte + (size_t)warp * Cv);
    const float4* x0 = (const float4*)xf;
    const float4* x1 = (const float4*)(xf + Cv);
    float s0 = 0.f, s1 = 0.f;
#pragma unroll
    for (int i = lane; i < Cv / 4; i += 32) {
        float4 w = w4[i];
        float4 a = x0[i];
        float4 c = x1[i];
        s0 += w.x * a.x + w.y * a.y + w.z * a.z + w.w * a.w;
        s1 += w.x * c.x + w.y * c.y + w.z * c.z + w.w * c.w;
    }
#pragma unroll
    for (int o = 16; o > 0; o >>= 1) {
        s0 += __shfl_down_sync(0xffffffffu, s0, o);
        s1 += __shfl_down_sync(0xffffffffu, s1, o);
    }
    if (lane == 0) {
        out[warp] = s0;
        out[Vv + warp] = s1;
    }
}

// ---------------------------------------------------------------------------
extern "C" void kernel_launch(void* const* d_in, const int* in_sizes, int n_in,
                              void* d_out, int out_size) {
    const int* idx = (const int*)d_in[0];
    const float* wte = (const float*)d_in[1];
    const float* wpe = (const float*)d_in[2];
    const float* ln1_w = (const float*)d_in[3];
    const float* ln1_b = (const float*)d_in[4];
    const float* attn_w = (const float*)d_in[5];
    const float* attn_b = (const float*)d_in[6];
    const float* proj_w = (const float*)d_in[7];
    const float* proj_b = (const float*)d_in[8];
    const float* ln2_w = (const float*)d_in[9];
    const float* ln2_b = (const float*)d_in[10];
    const float* fc_w = (const float*)d_in[11];
    const float* fc_b = (const float*)d_in[12];
    const float* fc2_w = (const float*)d_in[13];
    const float* fc2_b = (const float*)d_in[14];
    const float* lnf_w = (const float*)d_in[15];
    const float* lnf_b = (const float*)d_in[16];
    float* out = (float*)d_out;

    float* x;    cudaGetSymbolAddress((void**)&x, g_x);
    __half* ln;  cudaGetSymbolAddress((void**)&ln, g_ln);
    __half* qkv; cudaGetSymbolAddress((void**)&qkv, g_qkv);
    __half* o;   cudaGetSymbolAddress((void**)&o, g_o);
    __half* fc;  cudaGetSymbolAddress((void**)&fc, g_fc);
    float* xf;   cudaGetSymbolAddress((void**)&xf, g_xf);
    __half* wa;  cudaGetSymbolAddress((void**)&wa, g_wa);
    __half* wp;  cudaGetSymbolAddress((void**)&wp, g_wp);
    __half* wf;  cudaGetSymbolAddress((void**)&wf, g_wf);
    __half* wf2; cudaGetSymbolAddress((void**)&wf2, g_wf2);

    const int HSM256 = 3 * (256 * BKH + BN * BKH) * 2;  // 147456
    const int HSM64 = 3 * (64 * BKH + BN * BKH) * 2;    // 73728
    const int FSM = (FBR * HDv + 4 * FBC * HDv) * 2;    // 73728
    cudaFuncSetAttribute(hgemm_kernel<0, 256>, cudaFuncAttributeMaxDynamicSharedMemorySize, HSM256);
    cudaFuncSetAttribute(hgemm_kernel<2, 256>, cudaFuncAttributeMaxDynamicSharedMemorySize, HSM256);
    cudaFuncSetAttribute(hgemm_kernel<1, 64>, cudaFuncAttributeMaxDynamicSharedMemorySize, HSM64);
    cudaFuncSetAttribute(flash_kernel, cudaFuncAttributeMaxDynamicSharedMemorySize, FSM);

    {
        int total = N4A + N4P + 2 * N4F;
        f2h_all_kernel<<<(total + 255) / 256, 256>>>(attn_w, wa, proj_w, wp,
                                                     fc_w, wf, fc2_w, wf2);
    }

    embed_kernel<<<BTv, 256>>>(idx, wte, wpe, x);

    for (int l = 0; l < Lv; ++l) {
        layernorm_kernel<__half><<<BTv, 256>>>(x, Cv, ln1_w + l * Cv, ln1_b + l * Cv, ln, Cv);
        hgemm_kernel<0, 256><<<dim3(3 * Cv / BN, BTv / 256), 256, HSM256>>>(
            ln, wa + (size_t)l * 3 * Cv * Cv, attn_b + l * 3 * Cv, nullptr, qkv,
            BTv, 3 * Cv, Cv);
        flash_kernel<<<dim3(Tv / FBR, Bv * Hv), 128, FSM>>>(qkv, o);
        hgemm_kernel<1, 64><<<dim3(Cv / BN, BTv / 64), 256, HSM64>>>(
            o, wp + (size_t)l * Cv * Cv, proj_b + l * Cv, x, nullptr, BTv, Cv, Cv);
        layernorm_kernel<__half><<<BTv, 256>>>(x, Cv, ln2_w + l * Cv, ln2_b + l * Cv, ln, Cv);
        hgemm_kernel<2, 256><<<dim3(4 * Cv / BN, BTv / 256), 256, HSM256>>>(
            ln, wf + (size_t)l * 4 * Cv * Cv, fc_b + l * 4 * Cv, nullptr, fc, BTv,
            4 * Cv, Cv);
        hgemm_kernel<1, 64><<<dim3(Cv / BN, BTv / 64), 256, HSM64>>>(
            fc, wf2 + (size_t)l * 4 * Cv * Cv, fc2_b + l * Cv, x, nullptr, BTv, Cv,
            4 * Cv);
    }

    layernorm_kernel<float><<<Bv, 256>>>(x + (size_t)(Tv - 1) * Cv, (size_t)Tv * Cv,
                                         lnf_w, lnf_b, xf, Cv);
    int blocks = (Vv * 32 + 255) / 256;
    logits_kernel<<<blocks, 256>>>(xf, wte, out);
}

// round 7
// speedup vs baseline: 8.3971x; 1.0579x over previous
#include <cuda_runtime.h>
#include <cuda_fp16.h>
#include <math.h>
#include <stdint.h>

// ---------------------------------------------------------------------------
// GPT forward. fp16 mma.sync tensor cores, 3-stage pipelined GEMM (128x128
// tiles, 2 CTAs/SM), fused flash attention.
// B=2, T=1024, C=1024, L=4, H=16, HD=64, V=50257. Unmasked attention.
// ---------------------------------------------------------------------------

#define Bv 2
#define Tv 1024
#define Cv 1024
#define Lv 4
#define Hv 16
#define HDv 64
#define Vv 50257
#define BTv 2048
#define KQKV (3 * Cv)

// ---- scratch ---------------------------------------------------------------
__device__ float  g_x[BTv * Cv];
__device__ __half g_ln[BTv * Cv];
__device__ __half g_qkv[BTv * 3 * Cv];
__device__ __half g_o[BTv * Cv];
__device__ __half g_fc[BTv * 4 * Cv];
__device__ float  g_xf[Bv * Cv];
__device__ __half g_wa[Lv * 3 * Cv * Cv];
__device__ __half g_wp[Lv * Cv * Cv];
__device__ __half g_wf[Lv * 4 * Cv * Cv];
__device__ __half g_wf2[Lv * 4 * Cv * Cv];

// ---- PTX helpers ------------------------------------------------------------
__device__ __forceinline__ uint32_t cvta_s(const void* p) {
    return (uint32_t)__cvta_generic_to_shared(p);
}
__device__ __forceinline__ void cp_async16(uint32_t s, const void* g) {
    asm volatile("cp.async.cg.shared.global [%0], [%1], 16;" ::"r"(s), "l"(g));
}
__device__ __forceinline__ void cp_commit() {
    asm volatile("cp.async.commit_group;");
}
template <int N>
__device__ __forceinline__ void cp_wait() {
    asm volatile("cp.async.wait_group %0;" ::"n"(N));
}
__device__ __forceinline__ void ldsm_x4(uint32_t& r0, uint32_t& r1, uint32_t& r2,
                                        uint32_t& r3, uint32_t a) {
    asm volatile("ldmatrix.sync.aligned.m8n8.x4.shared.b16 {%0,%1,%2,%3}, [%4];"
                 : "=r"(r0), "=r"(r1), "=r"(r2), "=r"(r3) : "r"(a));
}
__device__ __forceinline__ void ldsm_x4t(uint32_t& r0, uint32_t& r1, uint32_t& r2,
                                         uint32_t& r3, uint32_t a) {
    asm volatile("ldmatrix.sync.aligned.m8n8.x4.trans.shared.b16 {%0,%1,%2,%3}, [%4];"
                 : "=r"(r0), "=r"(r1), "=r"(r2), "=r"(r3) : "r"(a));
}
__device__ __forceinline__ void mma16816(float* c, uint32_t a0, uint32_t a1,
                                         uint32_t a2, uint32_t a3, uint32_t b0,
                                         uint32_t b1) {
    asm volatile(
        "mma.sync.aligned.m16n8k16.row.col.f32.f16.f16.f32 "
        "{%0,%1,%2,%3}, {%4,%5,%6,%7}, {%8,%9}, {%0,%1,%2,%3};"
        : "+f"(c[0]), "+f"(c[1]), "+f"(c[2]), "+f"(c[3])
        : "r"(a0), "r"(a1), "r"(a2), "r"(a3), "r"(b0), "r"(b1));
}
__device__ __forceinline__ uint32_t pack_half2(float a, float b) {
    __half2 h = __floats2half2_rn(a, b);
    return *reinterpret_cast<uint32_t*>(&h);
}
// swizzled half-offset; tile row = 64 halves (8 x 16B chunks)
__device__ __forceinline__ uint32_t sw(int row, int kcol) {
    return (uint32_t)((row << 6) + ((((kcol >> 3) ^ (row & 7)) << 3) + (kcol & 7)));
}
__device__ __forceinline__ float gelu_f(float x) {
    return 0.5f * x * (1.0f + erff(x * 0.70710678118654752f));
}

// ---------------------------------------------------------------------------
// fused fp32->fp16 weight conversion (one launch)
// ---------------------------------------------------------------------------
#define N4A (Lv * 3 * Cv * Cv / 4)
#define N4P (Lv * Cv * Cv / 4)
#define N4F (Lv * 4 * Cv * Cv / 4)

__global__ void f2h_all_kernel(const float* __restrict__ sa, __half* __restrict__ da,
                               const float* __restrict__ sp, __half* __restrict__ dp,
                               const float* __restrict__ sf, __half* __restrict__ df,
                               const float* __restrict__ sf2, __half* __restrict__ df2) {
    int i = blockIdx.x * blockDim.x + threadIdx.x;
    const float* s;
    __half* d;
    if (i < N4A) {
        s = sa; d = da;
    } else if (i < N4A + N4P) {
        i -= N4A; s = sp; d = dp;
    } else if (i < N4A + N4P + N4F) {
        i -= N4A + N4P; s = sf; d = df;
    } else {
        i -= N4A + N4P + N4F; s = sf2; d = df2;
        if (i >= N4F) return;
    }
    float4 v = ((const float4*)s)[i];
    __half2* o = (__half2*)(d + (size_t)i * 4);
    o[0] = __floats2half2_rn(v.x, v.y);
    o[1] = __floats2half2_rn(v.z, v.w);
}

__global__ void embed_kernel(const int* __restrict__ idx,
                             const float* __restrict__ wte,
                             const float* __restrict__ wpe,
                             float* __restrict__ x) {
    int row = blockIdx.x;
    int t = row & (Tv - 1);
    int tok = idx[row];
    float4 va = ((const float4*)(wte + (size_t)tok * Cv))[threadIdx.x];
    float4 vp = ((const float4*)(wpe + (size_t)t * Cv))[threadIdx.x];
    ((float4*)(x + (size_t)row * Cv))[threadIdx.x] =
        make_float4(va.x + vp.x, va.y + vp.y, va.z + vp.z, va.w + vp.w);
}

// ---------------------------------------------------------------------------
template <typename OT>
__global__ void layernorm_kernel(const float* __restrict__ in, size_t in_stride,
                                 const float* __restrict__ w,
                                 const float* __restrict__ b,
                                 OT* __restrict__ out, size_t out_stride) {
    const float* p = in + (size_t)blockIdx.x * in_stride;
    int tid = threadIdx.x;
    float4 v = ((const float4*)p)[tid];
    float s = v.x + v.y + v.z + v.w;
    float ss = v.x * v.x + v.y * v.y + v.z * v.z + v.w * v.w;

    __shared__ float sm1[8], sm2[8];
    int lane = tid & 31, wid = tid >> 5;
#pragma unroll
    for (int o = 16; o > 0; o >>= 1) {
        s += __shfl_down_sync(0xffffffffu, s, o);
        ss += __shfl_down_sync(0xffffffffu, ss, o);
    }
    if (lane == 0) { sm1[wid] = s; sm2[wid] = ss; }
    __syncthreads();
    if (wid == 0) {
        s = (lane < 8) ? sm1[lane] : 0.f;
        ss = (lane < 8) ? sm2[lane] : 0.f;
#pragma unroll
        for (int o = 4; o > 0; o >>= 1) {
            s += __shfl_down_sync(0xffffffffu, s, o);
            ss += __shfl_down_sync(0xffffffffu, ss, o);
        }
        if (lane == 0) { sm1[0] = s; sm2[0] = ss; }
    }
    __syncthreads();
    float mean = sm1[0] * (1.0f / Cv);
    float var = sm2[0] * (1.0f / Cv) - mean * mean;
    float rstd = rsqrtf(var + 1e-5f);
    float4 w4 = ((const float4*)w)[tid];
    float4 b4 = ((const float4*)b)[tid];
    float y0 = (v.x - mean) * rstd * w4.x + b4.x;
    float y1 = (v.y - mean) * rstd * w4.y + b4.y;
    float y2 = (v.z - mean) * rstd * w4.z + b4.z;
    float y3 = (v.w - mean) * rstd * w4.w + b4.w;
    OT* op = out + (size_t)blockIdx.x * out_stride + tid * 4;
    if (sizeof(OT) == 2) {
        __half2* hp = (__half2*)op;
        hp[0] = __floats2half2_rn(y0, y1);
        hp[1] = __floats2half2_rn(y2, y3);
    } else {
        float4* fp = (float4*)op;
        *fp = make_float4(y0, y1, y2, y3);
    }
}

// ---------------------------------------------------------------------------
// Dense HGEMM: out[M,N] = A[M,K](half) @ W[N,K](half)^T + bias.
// CTA tile BMT x 128, BK=64, 3-stage cp.async pipeline, one barrier/stage.
// 256 threads, 8 warps (4m x 2n), warp tile (BMT/4) x 64. 2 CTAs/SM.
// EPI 0: half out. 1: fp32 residual in-place. 2: gelu half out.
// ---------------------------------------------------------------------------
#define BN 128
#define BKH 64

template <int EPI, int BMT>
__global__ __launch_bounds__(256, 2) void hgemm_kernel(
    const __half* __restrict__ A, const __half* __restrict__ W,
    const float* __restrict__ bias, float* __restrict__ resio,
    __half* __restrict__ outh, int M, int N, int K) {
    constexpr int S = 3;                 // pipeline stages
    constexpr int MT = BMT / 64;         // m16 tiles per warp
    constexpr int ASTG = BMT * BKH;      // halves per A stage
    constexpr int BSTG = BN * BKH;       // halves per B stage
    extern __shared__ __align__(16) __half smx[];
    __half* As = smx;              // S * ASTG
    __half* Bs = smx + S * ASTG;   // S * BSTG
    const int tid = threadIdx.x;
    const int lane = tid & 31;
    const int w = tid >> 5;
    const int wm = w >> 1;
    const int wn = w & 1;

    const __half* Ab = A + (size_t)(blockIdx.y * BMT) * K;
    const __half* Wb = W + (size_t)(blockIdx.x * BN) * K;
    uint32_t sA = cvta_s(As);
    uint32_t sB = cvta_s(Bs);

    float acc[MT][8][4];
#pragma unroll
    for (int i = 0; i < MT; i++)
#pragma unroll
        for (int j = 0; j < 8; j++)
#pragma unroll
            for (int q = 0; q < 4; q++) acc[i][j][q] = 0.f;

    const int KT = K / BKH;

    auto load_stage = [&](int kt) {
        int stg = kt % S;
        int koff = kt * BKH;
        uint32_t dA = sA + stg * ASTG * 2;
        uint32_t dB = sB + stg * BSTG * 2;
#pragma unroll
        for (int i = 0; i < BMT / 32; i++) {
            int g = tid + i * 256; int r = g >> 3; int c = g & 7;
            cp_async16(dA + sw(r, c * 8) * 2, Ab + (size_t)r * K + koff + c * 8);
        }
#pragma unroll
        for (int i = 0; i < BN / 32; i++) {
            int g = tid + i * 256; int r = g >> 3; int c = g & 7;
            cp_async16(dB + sw(r, c * 8) * 2, Wb + (size_t)r * K + koff + c * 8);
        }
        cp_commit();
    };

    load_stage(0);
    load_stage(1);

    for (int kt = 0; kt < KT; ++kt) {
        if (kt == KT - 1) cp_wait<0>(); else cp_wait<1>();
        __syncthreads();
        if (kt + 2 < KT) load_stage(kt + 2);

        int stg = kt % S;
        uint32_t aB = sA + (uint32_t)(stg * ASTG * 2);
        uint32_t bB = sB + (uint32_t)(stg * BSTG * 2);
#pragma unroll
        for (int ks = 0; ks < 4; ++ks) {
            int k0 = ks * 16;
            uint32_t af[MT][4];
#pragma unroll
            for (int mt = 0; mt < MT; ++mt) {
                int r = wm * (MT * 16) + mt * 16 + ((lane >> 3) & 1) * 8 + (lane & 7);
                int kc = k0 + ((lane >> 4) << 3);
                ldsm_x4(af[mt][0], af[mt][1], af[mt][2], af[mt][3],
                        aB + sw(r, kc) * 2);
            }
            // B fragments: one x4 covers two n-tiles (16 rows)
            uint32_t bf[4][4];
#pragma unroll
            for (int np = 0; np < 4; ++np) {
                int r = wn * 64 + np * 16 + (lane & 7) + (((lane >> 4) & 1) << 3);
                int kc = k0 + (((lane >> 3) & 1) << 3);
                ldsm_x4(bf[np][0], bf[np][1], bf[np][2], bf[np][3],
                        bB + sw(r, kc) * 2);
            }
#pragma unroll
            for (int mt = 0; mt < MT; ++mt)
#pragma unroll
                for (int np = 0; np < 4; ++np) {
                    mma16816(acc[mt][2 * np], af[mt][0], af[mt][1], af[mt][2],
                             af[mt][3], bf[np][0], bf[np][1]);
                    mma16816(acc[mt][2 * np + 1], af[mt][0], af[mt][1], af[mt][2],
                             af[mt][3], bf[np][2], bf[np][3]);
                }
        }
    }

    int g = lane >> 2, t = lane & 3;
#pragma unroll
    for (int mt = 0; mt < MT; ++mt) {
        int r0 = blockIdx.y * BMT + wm * (MT * 16) + mt * 16 + g;
#pragma unroll
        for (int nt = 0; nt < 8; ++nt) {
            int col = blockIdx.x * BN + wn * 64 + nt * 8 + 2 * t;
            float b0 = bias[col], b1 = bias[col + 1];
            float d0 = acc[mt][nt][0] + b0, d1 = acc[mt][nt][1] + b1;
            float d2 = acc[mt][nt][2] + b0, d3 = acc[mt][nt][3] + b1;
            if (EPI == 0) {
                *(__half2*)&outh[(size_t)r0 * N + col] = __floats2half2_rn(d0, d1);
                *(__half2*)&outh[(size_t)(r0 + 8) * N + col] = __floats2half2_rn(d2, d3);
            } else if (EPI == 1) {
                float2* p0 = (float2*)&resio[(size_t)r0 * N + col];
                float2 v0 = *p0; v0.x += d0; v0.y += d1; *p0 = v0;
                float2* p1 = (float2*)&resio[(size_t)(r0 + 8) * N + col];
                float2 v1 = *p1; v1.x += d2; v1.y += d3; *p1 = v1;
            } else {
                *(__half2*)&outh[(size_t)r0 * N + col] =
                    __floats2half2_rn(gelu_f(d0), gelu_f(d1));
                *(__half2*)&outh[(size_t)(r0 + 8) * N + col] =
                    __floats2half2_rn(gelu_f(d2), gelu_f(d3));
            }
        }
    }
}

// ---------------------------------------------------------------------------
// Fused flash attention (unmasked). Per CTA: 64 q rows of one (b,h).
// ---------------------------------------------------------------------------
#define FBR 64
#define FBC 128
#define FJT (Tv / FBC)  // 8

__global__ __launch_bounds__(128, 2) void flash_kernel(
    const __half* __restrict__ qkv, __half* __restrict__ o) {
    extern __shared__ __align__(16) __half fsm[];
    __half* Qs = fsm;
    __half* Ks = fsm + FBR * HDv;
    __half* Vs = Ks + 2 * FBC * HDv;
    const uint32_t sQ = cvta_s(Qs), sK = cvta_s(Ks), sV = cvta_s(Vs);
    const int tid = threadIdx.x;
    const int lane = tid & 31;
    const int w = tid >> 5;

    const int z = blockIdx.y, b = z >> 4, h = z & 15;
    const int i0 = blockIdx.x * FBR;
    const __half* qb = qkv + ((size_t)(b * Tv + i0)) * KQKV + h * HDv;
    const __half* kb = qkv + ((size_t)b * Tv) * KQKV + Cv + h * HDv;
    const __half* vb = kb + Cv;

    auto load_kv = [&](int jt) {
        int buf = jt & 1;
        int j0 = jt * FBC;
#pragma unroll
        for (int i = 0; i < 8; i++) {
            int g = tid + i * 128; int r = g >> 3; int c = g & 7;
            cp_async16(sK + (buf * FBC * HDv + sw(r, c * 8)) * 2,
                       kb + (size_t)(j0 + r) * KQKV + c * 8);
            cp_async16(sV + (buf * FBC * HDv + sw(r, c * 8)) * 2,
                       vb + (size_t)(j0 + r) * KQKV + c * 8);
        }
        cp_commit();
    };

#pragma unroll
    for (int i = 0; i < 4; i++) {
        int g = tid + i * 128; int r = g >> 3; int c = g & 7;
        cp_async16(sQ + sw(r, c * 8) * 2, qb + (size_t)r * KQKV + c * 8);
    }
    load_kv(0);

    float m0 = -1e30f, m1 = -1e30f, s0 = 0.f, s1 = 0.f;
    float acc_o[8][4];
#pragma unroll
    for (int i = 0; i < 8; i++)
#pragma unroll
        for (int q = 0; q < 4; q++) acc_o[i][q] = 0.f;

    uint32_t qf[4][4];

    for (int jt = 0; jt < FJT; ++jt) {
        int cur = jt & 1;
        cp_wait<0>();
        __syncthreads();
        if (jt + 1 < FJT) load_kv(jt + 1);

        if (jt == 0) {
#pragma unroll
            for (int ks = 0; ks < 4; ++ks) {
                int r = w * 16 + ((lane >> 3) & 1) * 8 + (lane & 7);
                int kc = ks * 16 + ((lane >> 4) << 3);
                ldsm_x4(qf[ks][0], qf[ks][1], qf[ks][2], qf[ks][3],
                        sQ + sw(r, kc) * 2);
            }
        }

        uint32_t kB = sK + (uint32_t)(cur * FBC * HDv * 2);
        uint32_t vB = sV + (uint32_t)(cur * FBC * HDv * 2);

        float acc_s[16][4];
#pragma unroll
        for (int i = 0; i < 16; i++)
#pragma unroll
            for (int q = 0; q < 4; q++) acc_s[i][q] = 0.f;

#pragma unroll
        for (int ks = 0; ks < 4; ++ks) {
            int k0 = ks * 16;
#pragma unroll
            for (int ntp = 0; ntp < 8; ++ntp) {
                uint32_t b0, b1, b2, b3;
                int r = ntp * 16 + (lane >> 4) * 8 + (lane & 7);
                int kc = k0 + ((lane >> 3) & 1) * 8;
                ldsm_x4(b0, b1, b2, b3, kB + sw(r, kc) * 2);
                mma16816(acc_s[2 * ntp], qf[ks][0], qf[ks][1], qf[ks][2],
                         qf[ks][3], b0, b1);
                mma16816(acc_s[2 * ntp + 1], qf[ks][0], qf[ks][1], qf[ks][2],
                         qf[ks][3], b2, b3);
            }
        }

        float m0n = m0, m1n = m1;
#pragma unroll
        for (int nt = 0; nt < 16; ++nt) {
            acc_s[nt][0] *= 0.125f; acc_s[nt][1] *= 0.125f;
            acc_s[nt][2] *= 0.125f; acc_s[nt][3] *= 0.125f;
            m0n = fmaxf(m0n, fmaxf(acc_s[nt][0], acc_s[nt][1]));
            m1n = fmaxf(m1n, fmaxf(acc_s[nt][2], acc_s[nt][3]));
        }
#pragma unroll
        for (int off = 1; off <= 2; off <<= 1) {
            m0n = fmaxf(m0n, __shfl_xor_sync(0xffffffffu, m0n, off));
            m1n = fmaxf(m1n, __shfl_xor_sync(0xffffffffu, m1n, off));
        }
        float alpha0 = __expf(m0 - m0n);
        float alpha1 = __expf(m1 - m1n);
        m0 = m0n; m1 = m1n;

        float r0 = 0.f, r1 = 0.f;
#pragma unroll
        for (int nt = 0; nt < 16; ++nt) {
            acc_s[nt][0] = __expf(acc_s[nt][0] - m0n);
            acc_s[nt][1] = __expf(acc_s[nt][1] - m0n);
            acc_s[nt][2] = __expf(acc_s[nt][2] - m1n);
            acc_s[nt][3] = __expf(acc_s[nt][3] - m1n);
            r0 += acc_s[nt][0] + acc_s[nt][1];
            r1 += acc_s[nt][2] + acc_s[nt][3];
        }
#pragma unroll
        for (int off = 1; off <= 2; off <<= 1) {
            r0 += __shfl_xor_sync(0xffffffffu, r0, off);
            r1 += __shfl_xor_sync(0xffffffffu, r1, off);
        }
        s0 = s0 * alpha0 + r0;
        s1 = s1 * alpha1 + r1;

#pragma unroll
        for (int nt = 0; nt < 8; ++nt) {
            acc_o[nt][0] *= alpha0; acc_o[nt][1] *= alpha0;
            acc_o[nt][2] *= alpha1; acc_o[nt][3] *= alpha1;
        }

#pragma unroll
        for (int kc = 0; kc < 8; ++kc) {
            uint32_t a0 = pack_half2(acc_s[2 * kc][0], acc_s[2 * kc][1]);
            uint32_t a1 = pack_half2(acc_s[2 * kc][2], acc_s[2 * kc][3]);
            uint32_t a2 = pack_half2(acc_s[2 * kc + 1][0], acc_s[2 * kc + 1][1]);
            uint32_t a3 = pack_half2(acc_s[2 * kc + 1][2], acc_s[2 * kc + 1][3]);
#pragma unroll
            for (int dp = 0; dp < 4; ++dp) {
                uint32_t b0, b1, b2, b3;
                int r = kc * 16 + ((lane >> 3) & 1) * 8 + (lane & 7);
                int c = dp * 16 + (lane >> 4) * 8;
                ldsm_x4t(b0, b1, b2, b3, vB + sw(r, c) * 2);
                mma16816(acc_o[2 * dp], a0, a1, a2, a3, b0, b1);
                mma16816(acc_o[2 * dp + 1], a0, a1, a2, a3, b2, b3);
            }
        }
    }

    float inv0 = 1.0f / s0, inv1 = 1.0f / s1;
    int g = lane >> 2, t = lane & 3;
    int ro0 = i0 + w * 16 + g;
#pragma unroll
    for (int nt = 0; nt < 8; ++nt) {
        int d = nt * 8 + 2 * t;
        *(__half2*)&o[((size_t)b * Tv + ro0) * Cv + h * HDv + d] =
            __floats2half2_rn(acc_o[nt][0] * inv0, acc_o[nt][1] * inv0);
        *(__half2*)&o[((size_t)b * Tv + ro0 + 8) * Cv + h * HDv + d] =
            __floats2half2_rn(acc_o[nt][2] * inv1, acc_o[nt][3] * inv1);
    }
}

// ---------------------------------------------------------------------------
__global__ void logits_kernel(const float* __restrict__ xf,
                              const float* __restrict__ wte,
                              float* __restrict__ out) {
    int warp = (blockIdx.x * blockDim.x + threadIdx.x) >> 5;
    int lane = threadIdx.x & 31;
    if (warp >= Vv) return;
    const float4* w4 = (const float4*)(wte + (size_t)warp * Cv);
    const float4* x0 = (const float4*)xf;
    const float4* x1 = (const float4*)(xf + Cv);
    float s0 = 0.f, s1 = 0.f;
#pragma unroll
    for (int i = lane; i < Cv / 4; i += 32) {
        float4 w = w4[i];
        float4 a = x0[i];
        float4 c = x1[i];
        s0 += w.x * a.x + w.y * a.y + w.z * a.z + w.w * a.w;
        s1 += w.x * c.x + w.y * c.y + w.z * c.z + w.w * c.w;
    }
#pragma unroll
    for (int o = 16; o > 0; o >>= 1) {
        s0 += __shfl_down_sync(0xffffffffu, s0, o);
        s1 += __shfl_down_sync(0xffffffffu, s1, o);
    }
    if (lane == 0) {
        out[warp] = s0;
        out[Vv + warp] = s1;
    }
}

// ---------------------------------------------------------------------------
extern "C" void kernel_launch(void* const* d_in, const int* in_sizes, int n_in,
                              void* d_out, int out_size) {
    const int* idx = (const int*)d_in[0];
    const float* wte = (const float*)d_in[1];
    const float* wpe = (const float*)d_in[2];
    const float* ln1_w = (const float*)d_in[3];
    const float* ln1_b = (const float*)d_in[4];
    const float* attn_w = (const float*)d_in[5];
    const float* attn_b = (const float*)d_in[6];
    const float* proj_w = (const float*)d_in[7];
    const float* proj_b = (const float*)d_in[8];
    const float* ln2_w = (const float*)d_in[9];
    const float* ln2_b = (const float*)d_in[10];
    const float* fc_w = (const float*)d_in[11];
    const float* fc_b = (const float*)d_in[12];
    const float* fc2_w = (const float*)d_in[13];
    const float* fc2_b = (const float*)d_in[14];
    const float* lnf_w = (const float*)d_in[15];
    const float* lnf_b = (const float*)d_in[16];
    float* out = (float*)d_out;

    float* x;    cudaGetSymbolAddress((void**)&x, g_x);
    __half* ln;  cudaGetSymbolAddress((void**)&ln, g_ln);
    __half* qkv; cudaGetSymbolAddress((void**)&qkv, g_qkv);
    __half* o;   cudaGetSymbolAddress((void**)&o, g_o);
    __half* fc;  cudaGetSymbolAddress((void**)&fc, g_fc);
    float* xf;   cudaGetSymbolAddress((void**)&xf, g_xf);
    __half* wa;  cudaGetSymbolAddress((void**)&wa, g_wa);
    __half* wp;  cudaGetSymbolAddress((void**)&wp, g_wp);
    __half* wf;  cudaGetSymbolAddress((void**)&wf, g_wf);
    __half* wf2; cudaGetSymbolAddress((void**)&wf2, g_wf2);

    const int HSM128 = 3 * (128 * BKH + BN * BKH) * 2;  // 98304
    const int HSM64 = 3 * (64 * BKH + BN * BKH) * 2;    // 73728
    const int FSM = (FBR * HDv + 4 * FBC * HDv) * 2;    // 73728
    cudaFuncSetAttribute(hgemm_kernel<0, 128>, cudaFuncAttributeMaxDynamicSharedMemorySize, HSM128);
    cudaFuncSetAttribute(hgemm_kernel<2, 128>, cudaFuncAttributeMaxDynamicSharedMemorySize, HSM128);
    cudaFuncSetAttribute(hgemm_kernel<1, 64>, cudaFuncAttributeMaxDynamicSharedMemorySize, HSM64);
    cudaFuncSetAttribute(flash_kernel, cudaFuncAttributeMaxDynamicSharedMemorySize, FSM);

    {
        int total = N4A + N4P + 2 * N4F;
        f2h_all_kernel<<<(total + 255) / 256, 256>>>(attn_w, wa, proj_w, wp,
                                                     fc_w, wf, fc2_w, wf2);
    }

    embed_kernel<<<BTv, 256>>>(idx, wte, wpe, x);

    for (int l = 0; l < Lv; ++l) {
        layernorm_kernel<__half><<<BTv, 256>>>(x, Cv, ln1_w + l * Cv, ln1_b + l * Cv, ln, Cv);
        hgemm_kernel<0, 128><<<dim3(3 * Cv / BN, BTv / 128), 256, HSM128>>>(
            ln, wa + (size_t)l * 3 * Cv * Cv, attn_b + l * 3 * Cv, nullptr, qkv,
            BTv, 3 * Cv, Cv);
        flash_kernel<<<dim3(Tv / FBR, Bv * Hv), 128, FSM>>>(qkv, o);
        hgemm_kernel<1, 64><<<dim3(Cv / BN, BTv / 64), 256, HSM64>>>(
            o, wp + (size_t)l * Cv * Cv, proj_b + l * Cv, x, nullptr, BTv, Cv, Cv);
        layernorm_kernel<__half><<<BTv, 256>>>(x, Cv, ln2_w + l * Cv, ln2_b + l * Cv, ln, Cv);
        hgemm_kernel<2, 128><<<dim3(4 * Cv / BN, BTv / 128), 256, HSM128>>>(
            ln, wf + (size_t)l * 4 * Cv * Cv, fc_b + l * 4 * Cv, nullptr, fc, BTv,
            4 * Cv, Cv);
        hgemm_kernel<1, 64><<<dim3(Cv / BN, BTv / 64), 256, HSM64>>>(
            fc, wf2 + (size_t)l * 4 * Cv * Cv, fc2_b + l * Cv, x, nullptr, BTv, Cv,
            4 * Cv);
    }

    layernorm_kernel<float><<<Bv, 256>>>(x + (size_t)(Tv - 1) * Cv, (size_t)Tv * Cv,
                                         lnf_w, lnf_b, xf, Cv);
    int blocks = (Vv * 32 + 255) / 256;
    logits_kernel<<<blocks, 256>>>(xf, wte, out);
}

// round 8
// speedup vs baseline: 8.4212x; 1.0029x over previous
#include <cuda_runtime.h>
#include <cuda_fp16.h>
#include <math.h>
#include <stdint.h>

// ---------------------------------------------------------------------------
// GPT forward. fp16 mma.sync tensor cores, 3-stage pipelined GEMM (128x128
// tiles, 2 CTAs/SM, rotated B-fragment pipeline), fused flash attention.
// B=2, T=1024, C=1024, L=4, H=16, HD=64, V=50257. Unmasked attention.
// ---------------------------------------------------------------------------

#define Bv 2
#define Tv 1024
#define Cv 1024
#define Lv 4
#define Hv 16
#define HDv 64
#define Vv 50257
#define BTv 2048
#define KQKV (3 * Cv)

// ---- scratch ---------------------------------------------------------------
__device__ float  g_x[BTv * Cv];
__device__ __half g_ln[BTv * Cv];
__device__ __half g_qkv[BTv * 3 * Cv];
__device__ __half g_o[BTv * Cv];
__device__ __half g_fc[BTv * 4 * Cv];
__device__ float  g_xf[Bv * Cv];
__device__ __half g_wa[Lv * 3 * Cv * Cv];
__device__ __half g_wp[Lv * Cv * Cv];
__device__ __half g_wf[Lv * 4 * Cv * Cv];
__device__ __half g_wf2[Lv * 4 * Cv * Cv];

// ---- PTX helpers ------------------------------------------------------------
__device__ __forceinline__ uint32_t cvta_s(const void* p) {
    return (uint32_t)__cvta_generic_to_shared(p);
}
__device__ __forceinline__ void cp_async16(uint32_t s, const void* g) {
    asm volatile("cp.async.cg.shared.global [%0], [%1], 16;" ::"r"(s), "l"(g));
}
__device__ __forceinline__ void cp_commit() {
    asm volatile("cp.async.commit_group;");
}
template <int N>
__device__ __forceinline__ void cp_wait() {
    asm volatile("cp.async.wait_group %0;" ::"n"(N));
}
__device__ __forceinline__ void ldsm_x4(uint32_t& r0, uint32_t& r1, uint32_t& r2,
                                        uint32_t& r3, uint32_t a) {
    asm volatile("ldmatrix.sync.aligned.m8n8.x4.shared.b16 {%0,%1,%2,%3}, [%4];"
                 : "=r"(r0), "=r"(r1), "=r"(r2), "=r"(r3) : "r"(a));
}
__device__ __forceinline__ void ldsm_x4t(uint32_t& r0, uint32_t& r1, uint32_t& r2,
                                         uint32_t& r3, uint32_t a) {
    asm volatile("ldmatrix.sync.aligned.m8n8.x4.trans.shared.b16 {%0,%1,%2,%3}, [%4];"
                 : "=r"(r0), "=r"(r1), "=r"(r2), "=r"(r3) : "r"(a));
}
__device__ __forceinline__ void mma16816(float* c, uint32_t a0, uint32_t a1,
                                         uint32_t a2, uint32_t a3, uint32_t b0,
                                         uint32_t b1) {
    asm volatile(
        "mma.sync.aligned.m16n8k16.row.col.f32.f16.f16.f32 "
        "{%0,%1,%2,%3}, {%4,%5,%6,%7}, {%8,%9}, {%0,%1,%2,%3};"
        : "+f"(c[0]), "+f"(c[1]), "+f"(c[2]), "+f"(c[3])
        : "r"(a0), "r"(a1), "r"(a2), "r"(a3), "r"(b0), "r"(b1));
}
__device__ __forceinline__ uint32_t pack_half2(float a, float b) {
    __half2 h = __floats2half2_rn(a, b);
    return *reinterpret_cast<uint32_t*>(&h);
}
// swizzled half-offset; tile row = 64 halves (8 x 16B chunks)
__device__ __forceinline__ uint32_t sw(int row, int kcol) {
    return (uint32_t)((row << 6) + ((((kcol >> 3) ^ (row & 7)) << 3) + (kcol & 7)));
}
__device__ __forceinline__ float gelu_f(float x) {
    return 0.5f * x * (1.0f + erff(x * 0.70710678118654752f));
}

// ---------------------------------------------------------------------------
// fused fp32->fp16 weight conversion (one launch)
// ---------------------------------------------------------------------------
#define N4A (Lv * 3 * Cv * Cv / 4)
#define N4P (Lv * Cv * Cv / 4)
#define N4F (Lv * 4 * Cv * Cv / 4)

__global__ void f2h_all_kernel(const float* __restrict__ sa, __half* __restrict__ da,
                               const float* __restrict__ sp, __half* __restrict__ dp,
                               const float* __restrict__ sf, __half* __restrict__ df,
                               const float* __restrict__ sf2, __half* __restrict__ df2) {
    int i = blockIdx.x * blockDim.x + threadIdx.x;
    const float* s;
    __half* d;
    if (i < N4A) {
        s = sa; d = da;
    } else if (i < N4A + N4P) {
        i -= N4A; s = sp; d = dp;
    } else if (i < N4A + N4P + N4F) {
        i -= N4A + N4P; s = sf; d = df;
    } else {
        i -= N4A + N4P + N4F; s = sf2; d = df2;
        if (i >= N4F) return;
    }
    float4 v = ((const float4*)s)[i];
    __half2* o = (__half2*)(d + (size_t)i * 4);
    o[0] = __floats2half2_rn(v.x, v.y);
    o[1] = __floats2half2_rn(v.z, v.w);
}

__global__ void embed_kernel(const int* __restrict__ idx,
                             const float* __restrict__ wte,
                             const float* __restrict__ wpe,
                             float* __restrict__ x) {
    int row = blockIdx.x;
    int t = row & (Tv - 1);
    int tok = idx[row];
    float4 va = ((const float4*)(wte + (size_t)tok * Cv))[threadIdx.x];
    float4 vp = ((const float4*)(wpe + (size_t)t * Cv))[threadIdx.x];
    ((float4*)(x + (size_t)row * Cv))[threadIdx.x] =
        make_float4(va.x + vp.x, va.y + vp.y, va.z + vp.z, va.w + vp.w);
}

// ---------------------------------------------------------------------------
template <typename OT>
__global__ void layernorm_kernel(const float* __restrict__ in, size_t in_stride,
                                 const float* __restrict__ w,
                                 const float* __restrict__ b,
                                 OT* __restrict__ out, size_t out_stride) {
    const float* p = in + (size_t)blockIdx.x * in_stride;
    int tid = threadIdx.x;
    float4 v = ((const float4*)p)[tid];
    float s = v.x + v.y + v.z + v.w;
    float ss = v.x * v.x + v.y * v.y + v.z * v.z + v.w * v.w;

    __shared__ float sm1[8], sm2[8];
    int lane = tid & 31, wid = tid >> 5;
#pragma unroll
    for (int o = 16; o > 0; o >>= 1) {
        s += __shfl_down_sync(0xffffffffu, s, o);
        ss += __shfl_down_sync(0xffffffffu, ss, o);
    }
    if (lane == 0) { sm1[wid] = s; sm2[wid] = ss; }
    __syncthreads();
    if (wid == 0) {
        s = (lane < 8) ? sm1[lane] : 0.f;
        ss = (lane < 8) ? sm2[lane] : 0.f;
#pragma unroll
        for (int o = 4; o > 0; o >>= 1) {
            s += __shfl_down_sync(0xffffffffu, s, o);
            ss += __shfl_down_sync(0xffffffffu, ss, o);
        }
        if (lane == 0) { sm1[0] = s; sm2[0] = ss; }
    }
    __syncthreads();
    float mean = sm1[0] * (1.0f / Cv);
    float var = sm2[0] * (1.0f / Cv) - mean * mean;
    float rstd = rsqrtf(var + 1e-5f);
    float4 w4 = ((const float4*)w)[tid];
    float4 b4 = ((const float4*)b)[tid];
    float y0 = (v.x - mean) * rstd * w4.x + b4.x;
    float y1 = (v.y - mean) * rstd * w4.y + b4.y;
    float y2 = (v.z - mean) * rstd * w4.z + b4.z;
    float y3 = (v.w - mean) * rstd * w4.w + b4.w;
    OT* op = out + (size_t)blockIdx.x * out_stride + tid * 4;
    if (sizeof(OT) == 2) {
        __half2* hp = (__half2*)op;
        hp[0] = __floats2half2_rn(y0, y1);
        hp[1] = __floats2half2_rn(y2, y3);
    } else {
        float4* fp = (float4*)op;
        *fp = make_float4(y0, y1, y2, y3);
    }
}

// ---------------------------------------------------------------------------
// Dense HGEMM: out[M,N] = A[M,K](half) @ W[N,K](half)^T + bias.
// CTA tile BMT x 128, BK=64, 3-stage cp.async pipeline, one barrier/stage.
// 256 threads, 8 warps (4m x 2n). Rotating B-fragment buffer to cut register
// liveness (bf: 8 live regs instead of 16) and overlap ldsm with mma.
// EPI 0: half out. 1: fp32 residual in-place. 2: gelu half out.
// ---------------------------------------------------------------------------
#define BN 128
#define BKH 64

template <int EPI, int BMT>
__global__ __launch_bounds__(256, 2) void hgemm_kernel(
    const __half* __restrict__ A, const __half* __restrict__ W,
    const float* __restrict__ bias, float* __restrict__ resio,
    __half* __restrict__ outh, int M, int N, int K) {
    constexpr int S = 3;
    constexpr int MT = BMT / 64;
    constexpr int ASTG = BMT * BKH;
    constexpr int BSTG = BN * BKH;
    extern __shared__ __align__(16) __half smx[];
    __half* As = smx;
    __half* Bs = smx + S * ASTG;
    const int tid = threadIdx.x;
    const int lane = tid & 31;
    const int w = tid >> 5;
    const int wm = w >> 1;
    const int wn = w & 1;

    const __half* Ab = A + (size_t)(blockIdx.y * BMT) * K;
    const __half* Wb = W + (size_t)(blockIdx.x * BN) * K;
    uint32_t sA = cvta_s(As);
    uint32_t sB = cvta_s(Bs);

    float acc[MT][8][4];
#pragma unroll
    for (int i = 0; i < MT; i++)
#pragma unroll
        for (int j = 0; j < 8; j++)
#pragma unroll
            for (int q = 0; q < 4; q++) acc[i][j][q] = 0.f;

    const int KT = K / BKH;

    auto load_stage = [&](int kt) {
        int stg = kt % S;
        int koff = kt * BKH;
        uint32_t dA = sA + stg * ASTG * 2;
        uint32_t dB = sB + stg * BSTG * 2;
#pragma unroll
        for (int i = 0; i < BMT / 32; i++) {
            int g = tid + i * 256; int r = g >> 3; int c = g & 7;
            cp_async16(dA + sw(r, c * 8) * 2, Ab + (size_t)r * K + koff + c * 8);
        }
#pragma unroll
        for (int i = 0; i < BN / 32; i++) {
            int g = tid + i * 256; int r = g >> 3; int c = g & 7;
            cp_async16(dB + sw(r, c * 8) * 2, Wb + (size_t)r * K + koff + c * 8);
        }
        cp_commit();
    };

    load_stage(0);
    load_stage(1);

    // B fragment address helper (row group np covers n-tiles 2np, 2np+1)
    auto bf_addr = [&](uint32_t bB, int k0, int np) -> uint32_t {
        int r = wn * 64 + np * 16 + (lane & 7) + (((lane >> 4) & 1) << 3);
        int kc = k0 + (((lane >> 3) & 1) << 3);
        return bB + sw(r, kc) * 2;
    };

    for (int kt = 0; kt < KT; ++kt) {
        if (kt == KT - 1) cp_wait<0>(); else cp_wait<1>();
        __syncthreads();
        if (kt + 2 < KT) load_stage(kt + 2);

        int stg = kt % S;
        uint32_t aB = sA + (uint32_t)(stg * ASTG * 2);
        uint32_t bB = sB + (uint32_t)(stg * BSTG * 2);
#pragma unroll
        for (int ks = 0; ks < 4; ++ks) {
            int k0 = ks * 16;
            uint32_t af[MT][4];
#pragma unroll
            for (int mt = 0; mt < MT; ++mt) {
                int r = wm * (MT * 16) + mt * 16 + ((lane >> 3) & 1) * 8 + (lane & 7);
                int kc = k0 + ((lane >> 4) << 3);
                ldsm_x4(af[mt][0], af[mt][1], af[mt][2], af[mt][3],
                        aB + sw(r, kc) * 2);
            }
            // rotating B fragment buffer: prefetch np+1 before mma of np
            uint32_t bf0[4];
            ldsm_x4(bf0[0], bf0[1], bf0[2], bf0[3], bf_addr(bB, k0, 0));
#pragma unroll
            for (int np = 0; np < 4; ++np) {
                uint32_t bf1[4];
                if (np < 3)
                    ldsm_x4(bf1[0], bf1[1], bf1[2], bf1[3], bf_addr(bB, k0, np + 1));
#pragma unroll
                for (int mt = 0; mt < MT; ++mt) {
                    mma16816(acc[mt][2 * np], af[mt][0], af[mt][1], af[mt][2],
                             af[mt][3], bf0[0], bf0[1]);
                    mma16816(acc[mt][2 * np + 1], af[mt][0], af[mt][1], af[mt][2],
                             af[mt][3], bf0[2], bf0[3]);
                }
                if (np < 3) {
                    bf0[0] = bf1[0]; bf0[1] = bf1[1];
                    bf0[2] = bf1[2]; bf0[3] = bf1[3];
                }
            }
        }
    }

    int g = lane >> 2, t = lane & 3;
#pragma unroll
    for (int mt = 0; mt < MT; ++mt) {
        int r0 = blockIdx.y * BMT + wm * (MT * 16) + mt * 16 + g;
#pragma unroll
        for (int nt = 0; nt < 8; ++nt) {
            int col = blockIdx.x * BN + wn * 64 + nt * 8 + 2 * t;
            float b0 = bias[col], b1 = bias[col + 1];
            float d0 = acc[mt][nt][0] + b0, d1 = acc[mt][nt][1] + b1;
            float d2 = acc[mt][nt][2] + b0, d3 = acc[mt][nt][3] + b1;
            if (EPI == 0) {
                *(__half2*)&outh[(size_t)r0 * N + col] = __floats2half2_rn(d0, d1);
                *(__half2*)&outh[(size_t)(r0 + 8) * N + col] = __floats2half2_rn(d2, d3);
            } else if (EPI == 1) {
                float2* p0 = (float2*)&resio[(size_t)r0 * N + col];
                float2 v0 = *p0; v0.x += d0; v0.y += d1; *p0 = v0;
                float2* p1 = (float2*)&resio[(size_t)(r0 + 8) * N + col];
                float2 v1 = *p1; v1.x += d2; v1.y += d3; *p1 = v1;
            } else {
                *(__half2*)&outh[(size_t)r0 * N + col] =
                    __floats2half2_rn(gelu_f(d0), gelu_f(d1));
                *(__half2*)&outh[(size_t)(r0 + 8) * N + col] =
                    __floats2half2_rn(gelu_f(d2), gelu_f(d3));
            }
        }
    }
}

// ---------------------------------------------------------------------------
// Fused flash attention (unmasked). Per CTA: 64 q rows of one (b,h).
// 3 CTAs/SM target (smem 72KB x 3 = 216KB).
// ---------------------------------------------------------------------------
#define FBR 64
#define FBC 128
#define FJT (Tv / FBC)  // 8

__global__ __launch_bounds__(128, 3) void flash_kernel(
    const __half* __restrict__ qkv, __half* __restrict__ o) {
    extern __shared__ __align__(16) __half fsm[];
    __half* Qs = fsm;
    __half* Ks = fsm + FBR * HDv;
    __half* Vs = Ks + 2 * FBC * HDv;
    const uint32_t sQ = cvta_s(Qs), sK = cvta_s(Ks), sV = cvta_s(Vs);
    const int tid = threadIdx.x;
    const int lane = tid & 31;
    const int w = tid >> 5;

    const int z = blockIdx.y, b = z >> 4, h = z & 15;
    const int i0 = blockIdx.x * FBR;
    const __half* qb = qkv + ((size_t)(b * Tv + i0)) * KQKV + h * HDv;
    const __half* kb = qkv + ((size_t)b * Tv) * KQKV + Cv + h * HDv;
    const __half* vb = kb + Cv;

    auto load_kv = [&](int jt) {
        int buf = jt & 1;
        int j0 = jt * FBC;
#pragma unroll
        for (int i = 0; i < 8; i++) {
            int g = tid + i * 128; int r = g >> 3; int c = g & 7;
            cp_async16(sK + (buf * FBC * HDv + sw(r, c * 8)) * 2,
                       kb + (size_t)(j0 + r) * KQKV + c * 8);
            cp_async16(sV + (buf * FBC * HDv + sw(r, c * 8)) * 2,
                       vb + (size_t)(j0 + r) * KQKV + c * 8);
        }
        cp_commit();
    };

#pragma unroll
    for (int i = 0; i < 4; i++) {
        int g = tid + i * 128; int r = g >> 3; int c = g & 7;
        cp_async16(sQ + sw(r, c * 8) * 2, qb + (size_t)r * KQKV + c * 8);
    }
    load_kv(0);

    float m0 = -1e30f, m1 = -1e30f, s0 = 0.f, s1 = 0.f;
    float acc_o[8][4];
#pragma unroll
    for (int i = 0; i < 8; i++)
#pragma unroll
        for (int q = 0; q < 4; q++) acc_o[i][q] = 0.f;

    uint32_t qf[4][4];

    for (int jt = 0; jt < FJT; ++jt) {
        int cur = jt & 1;
        cp_wait<0>();
        __syncthreads();
        if (jt + 1 < FJT) load_kv(jt + 1);

        if (jt == 0) {
#pragma unroll
            for (int ks = 0; ks < 4; ++ks) {
                int r = w * 16 + ((lane >> 3) & 1) * 8 + (lane & 7);
                int kc = ks * 16 + ((lane >> 4) << 3);
                ldsm_x4(qf[ks][0], qf[ks][1], qf[ks][2], qf[ks][3],
                        sQ + sw(r, kc) * 2);
            }
        }

        uint32_t kB = sK + (uint32_t)(cur * FBC * HDv * 2);
        uint32_t vB = sV + (uint32_t)(cur * FBC * HDv * 2);

        float acc_s[16][4];
#pragma unroll
        for (int i = 0; i < 16; i++)
#pragma unroll
            for (int q = 0; q < 4; q++) acc_s[i][q] = 0.f;

#pragma unroll
        for (int ks = 0; ks < 4; ++ks) {
            int k0 = ks * 16;
#pragma unroll
            for (int ntp = 0; ntp < 8; ++ntp) {
                uint32_t b0, b1, b2, b3;
                int r = ntp * 16 + (lane >> 4) * 8 + (lane & 7);
                int kc = k0 + ((lane >> 3) & 1) * 8;
                ldsm_x4(b0, b1, b2, b3, kB + sw(r, kc) * 2);
                mma16816(acc_s[2 * ntp], qf[ks][0], qf[ks][1], qf[ks][2],
                         qf[ks][3], b0, b1);
                mma16816(acc_s[2 * ntp + 1], qf[ks][0], qf[ks][1], qf[ks][2],
                         qf[ks][3], b2, b3);
            }
        }

        float m0n = m0, m1n = m1;
#pragma unroll
        for (int nt = 0; nt < 16; ++nt) {
            acc_s[nt][0] *= 0.125f; acc_s[nt][1] *= 0.125f;
            acc_s[nt][2] *= 0.125f; acc_s[nt][3] *= 0.125f;
            m0n = fmaxf(m0n, fmaxf(acc_s[nt][0], acc_s[nt][1]));
            m1n = fmaxf(m1n, fmaxf(acc_s[nt][2], acc_s[nt][3]));
        }
#pragma unroll
        for (int off = 1; off <= 2; off <<= 1) {
            m0n = fmaxf(m0n, __shfl_xor_sync(0xffffffffu, m0n, off));
            m1n = fmaxf(m1n, __shfl_xor_sync(0xffffffffu, m1n, off));
        }
        float alpha0 = __expf(m0 - m0n);
        float alpha1 = __expf(m1 - m1n);
        m0 = m0n; m1 = m1n;

        float r0 = 0.f, r1 = 0.f;
#pragma unroll
        for (int nt = 0; nt < 16; ++nt) {
            acc_s[nt][0] = __expf(acc_s[nt][0] - m0n);
            acc_s[nt][1] = __expf(acc_s[nt][1] - m0n);
            acc_s[nt][2] = __expf(acc_s[nt][2] - m1n);
            acc_s[nt][3] = __expf(acc_s[nt][3] - m1n);
            r0 += acc_s[nt][0] + acc_s[nt][1];
            r1 += acc_s[nt][2] + acc_s[nt][3];
        }
#pragma unroll
        for (int off = 1; off <= 2; off <<= 1) {
            r0 += __shfl_xor_sync(0xffffffffu, r0, off);
            r1 += __shfl_xor_sync(0xffffffffu, r1, off);
        }
        s0 = s0 * alpha0 + r0;
        s1 = s1 * alpha1 + r1;

#pragma unroll
        for (int nt = 0; nt < 8; ++nt) {
            acc_o[nt][0] *= alpha0; acc_o[nt][1] *= alpha0;
            acc_o[nt][2] *= alpha1; acc_o[nt][3] *= alpha1;
        }

#pragma unroll
        for (int kc = 0; kc < 8; ++kc) {
            uint32_t a0 = pack_half2(acc_s[2 * kc][0], acc_s[2 * kc][1]);
            uint32_t a1 = pack_half2(acc_s[2 * kc][2], acc_s[2 * kc][3]);
            uint32_t a2 = pack_half2(acc_s[2 * kc + 1][0], acc_s[2 * kc + 1][1]);
            uint32_t a3 = pack_half2(acc_s[2 * kc + 1][2], acc_s[2 * kc + 1][3]);
#pragma unroll
            for (int dp = 0; dp < 4; ++dp) {
                uint32_t b0, b1, b2, b3;
                int r = kc * 16 + ((lane >> 3) & 1) * 8 + (lane & 7);
                int c = dp * 16 + (lane >> 4) * 8;
                ldsm_x4t(b0, b1, b2, b3, vB + sw(r, c) * 2);
                mma16816(acc_o[2 * dp], a0, a1, a2, a3, b0, b1);
                mma16816(acc_o[2 * dp + 1], a0, a1, a2, a3, b2, b3);
            }
        }
    }

    float inv0 = 1.0f / s0, inv1 = 1.0f / s1;
    int g = lane >> 2, t = lane & 3;
    int ro0 = i0 + w * 16 + g;
#pragma unroll
    for (int nt = 0; nt < 8; ++nt) {
        int d = nt * 8 + 2 * t;
        *(__half2*)&o[((size_t)b * Tv + ro0) * Cv + h * HDv + d] =
            __floats2half2_rn(acc_o[nt][0] * inv0, acc_o[nt][1] * inv0);
        *(__half2*)&o[((size_t)b * Tv + ro0 + 8) * Cv + h * HDv + d] =
            __floats2half2_rn(acc_o[nt][2] * inv1, acc_o[nt][3] * inv1);
    }
}

// ---------------------------------------------------------------------------
__global__ void logits_kernel(const float* __restrict__ xf,
                              const float* __restrict__ wte,
                              float* __restrict__ out) {
    int warp = (blockIdx.x * blockDim.x + threadIdx.x) >> 5;
    int lane = threadIdx.x & 31;
    if (warp >= Vv) return;
    const float4* w4 = (const float4*)(wte + (size_t)warp * Cv);
    const float4* x0 = (const float4*)xf;
    const float4* x1 = (const float4*)(xf + Cv);
    float s0 = 0.f, s1 = 0.f;
#pragma unroll
    for (int i = lane; i < Cv / 4; i += 32) {
        float4 w = w4[i];
        float4 a = x0[i];
        float4 c = x1[i];
        s0 += w.x * a.x + w.y * a.y + w.z * a.z + w.w * a.w;
        s1 += w.x * c.x + w.y * c.y + w.z * c.z + w.w * c.w;
    }
#pragma unroll
    for (int o = 16; o > 0; o >>= 1) {
        s0 += __shfl_down_sync(0xffffffffu, s0, o);
        s1 += __shfl_down_sync(0xffffffffu, s1, o);
    }
    if (lane == 0) {
        out[warp] = s0;
        out[Vv + warp] = s1;
    }
}

// ---------------------------------------------------------------------------
extern "C" void kernel_launch(void* const* d_in, const int* in_sizes, int n_in,
                              void* d_out, int out_size) {
    const int* idx = (const int*)d_in[0];
    const float* wte = (const float*)d_in[1];
    const float* wpe = (const float*)d_in[2];
    const float* ln1_w = (const float*)d_in[3];
    const float* ln1_b = (const float*)d_in[4];
    const float* attn_w = (const float*)d_in[5];
    const float* attn_b = (const float*)d_in[6];
    const float* proj_w = (const float*)d_in[7];
    const float* proj_b = (const float*)d_in[8];
    const float* ln2_w = (const float*)d_in[9];
    const float* ln2_b = (const float*)d_in[10];
    const float* fc_w = (const float*)d_in[11];
    const float* fc_b = (const float*)d_in[12];
    const float* fc2_w = (const float*)d_in[13];
    const float* fc2_b = (const float*)d_in[14];
    const float* lnf_w = (const float*)d_in[15];
    const float* lnf_b = (const float*)d_in[16];
    float* out = (float*)d_out;

    float* x;    cudaGetSymbolAddress((void**)&x, g_x);
    __half* ln;  cudaGetSymbolAddress((void**)&ln, g_ln);
    __half* qkv; cudaGetSymbolAddress((void**)&qkv, g_qkv);
    __half* o;   cudaGetSymbolAddress((void**)&o, g_o);
    __half* fc;  cudaGetSymbolAddress((void**)&fc, g_fc);
    float* xf;   cudaGetSymbolAddress((void**)&xf, g_xf);
    __half* wa;  cudaGetSymbolAddress((void**)&wa, g_wa);
    __half* wp;  cudaGetSymbolAddress((void**)&wp, g_wp);
    __half* wf;  cudaGetSymbolAddress((void**)&wf, g_wf);
    __half* wf2; cudaGetSymbolAddress((void**)&wf2, g_wf2);

    const int HSM128 = 3 * (128 * BKH + BN * BKH) * 2;  // 98304
    const int HSM64 = 3 * (64 * BKH + BN * BKH) * 2;    // 73728
    const int FSM = (FBR * HDv + 4 * FBC * HDv) * 2;    // 73728
    cudaFuncSetAttribute(hgemm_kernel<0, 128>, cudaFuncAttributeMaxDynamicSharedMemorySize, HSM128);
    cudaFuncSetAttribute(hgemm_kernel<2, 128>, cudaFuncAttributeMaxDynamicSharedMemorySize, HSM128);
    cudaFuncSetAttribute(hgemm_kernel<1, 64>, cudaFuncAttributeMaxDynamicSharedMemorySize, HSM64);
    cudaFuncSetAttribute(flash_kernel, cudaFuncAttributeMaxDynamicSharedMemorySize, FSM);

    {
        int total = N4A + N4P + 2 * N4F;
        f2h_all_kernel<<<(total + 255) / 256, 256>>>(attn_w, wa, proj_w, wp,
                                                     fc_w, wf, fc2_w, wf2);
    }

    embed_kernel<<<BTv, 256>>>(idx, wte, wpe, x);

    for (int l = 0; l < Lv; ++l) {
        layernorm_kernel<__half><<<BTv, 256>>>(x, Cv, ln1_w + l * Cv, ln1_b + l * Cv, ln, Cv);
        hgemm_kernel<0, 128><<<dim3(3 * Cv / BN, BTv / 128), 256, HSM128>>>(
            ln, wa + (size_t)l * 3 * Cv * Cv, attn_b + l * 3 * Cv, nullptr, qkv,
            BTv, 3 * Cv, Cv);
        flash_kernel<<<dim3(Tv / FBR, Bv * Hv), 128, FSM>>>(qkv, o);
        hgemm_kernel<1, 64><<<dim3(Cv / BN, BTv / 64), 256, HSM64>>>(
            o, wp + (size_t)l * Cv * Cv, proj_b + l * Cv, x, nullptr, BTv, Cv, Cv);
        layernorm_kernel<__half><<<BTv, 256>>>(x, Cv, ln2_w + l * Cv, ln2_b + l * Cv, ln, Cv);
        hgemm_kernel<2, 128><<<dim3(4 * Cv / BN, BTv / 128), 256, HSM128>>>(
            ln, wf + (size_t)l * 4 * Cv * Cv, fc_b + l * 4 * Cv, nullptr, fc, BTv,
            4 * Cv, Cv);
        hgemm_kernel<1, 64><<<dim3(Cv / BN, BTv / 64), 256, HSM64>>>(
            fc, wf2 + (size_t)l * 4 * Cv * Cv, fc2_b + l * Cv, x, nullptr, BTv, Cv,
            4 * Cv);
    }

    layernorm_kernel<float><<<Bv, 256>>>(x + (size_t)(Tv - 1) * Cv, (size_t)Tv * Cv,
                                         lnf_w, lnf_b, xf, Cv);
    int blocks = (Vv * 32 + 255) / 256;
    logits_kernel<<<blocks, 256>>>(xf, wte, out);
}